// round 12
// baseline (speedup 1.0000x reference)
#include <cuda_runtime.h>
#include <cuda_bf16.h>
#include <math.h>
#include <stdint.h>

// ---------------- problem constants (fixed-shape problem) ----------------
#define T_TOK 8192
#define DIM   2048
#define HID   8192
#define EPS_P 1e-4f
#define RMS_EPS 1e-5f

// smem tile geometry: rows x 32 tf32, row stride 36 floats (conflict-free)
#define SK    36
#define TILEF 4608    // 128*36 floats per 128-row operand tile
#define STGF2 13824   // 384*36 floats per stage (256-row A + 128-row B)
#define GN    16      // band width (n-tiles) for the L2 swizzle

// ---------------- scratch (static device globals; no allocs) -------------
__device__ float g_xhi [(size_t)T_TOK * DIM];
__device__ float g_xlo [(size_t)T_TOK * DIM];
__device__ float g_wqth[(size_t)DIM * DIM];
__device__ float g_wqtl[(size_t)DIM * DIM];
__device__ float g_wkth[(size_t)DIM * DIM];
__device__ float g_wktl[(size_t)DIM * DIM];
__device__ float g_fc1t[(size_t)2 * HID * DIM];
__device__ float g_fc2t[(size_t)DIM * HID];
__device__ float g_q  [(size_t)T_TOK * DIM];
__device__ float g_k  [(size_t)T_TOK * DIM];
__device__ float g_xn [(size_t)T_TOK * DIM];
__device__ float g_s  [(size_t)T_TOK * HID];
__device__ float g_z  [(size_t)T_TOK * DIM];
__device__ float g_nq [T_TOK];
__device__ float g_nk [T_TOK];
__device__ float g_dqk[T_TOK];
__device__ float g_a  [T_TOK];
__device__ float g_c  [T_TOK];

// ---------------- PTX helpers ----------------
__device__ __forceinline__ uint32_t smem_u32(const void* p) {
    uint32_t a;
    asm("{ .reg .u64 t; cvta.to.shared.u64 t, %1; cvt.u32.u64 %0, t; }" : "=r"(a) : "l"(p));
    return a;
}
__device__ __forceinline__ float tf32_rna(float v) {
    uint32_t r;
    asm("cvt.rna.tf32.f32 %0, %1;" : "=r"(r) : "f"(v));
    return __uint_as_float(r);
}
__device__ __forceinline__ void cp16(uint32_t dst, const float* src) {
    asm volatile("cp.async.cg.shared.global [%0], [%1], 16;" :: "r"(dst), "l"(src) : "memory");
}
__device__ __forceinline__ void cp_commit() {
    asm volatile("cp.async.commit_group;" ::: "memory");
}
template<int N> __device__ __forceinline__ void cp_wait() {
    asm volatile("cp.async.wait_group %0;" :: "n"(N) : "memory");
}

// m16n8k8 row.col tf32 MMA: D += A*B, fp32 accumulate
#define MMA8(c, a, b0, b1)                                                      \
    asm volatile(                                                               \
        "mma.sync.aligned.m16n8k8.row.col.f32.tf32.tf32.f32 "                   \
        "{%0,%1,%2,%3}, {%4,%5,%6,%7}, {%8,%9}, {%0,%1,%2,%3};"                 \
        : "+f"((c)[0]), "+f"((c)[1]), "+f"((c)[2]), "+f"((c)[3])                \
        : "r"((a)[0]), "r"((a)[1]), "r"((a)[2]), "r"((a)[3]),                   \
          "r"(b0), "r"(b1))

// band swizzle: 1D grid -> (m_tile, n_tile); m fastest inside a GN-wide band
__device__ __forceinline__ void swz_tile(int bid, int tiles_m, int& mt, int& nt) {
    const int per_band = GN * tiles_m;
    const int band = bid / per_band;
    const int loc  = bid % per_band;
    mt = loc / GN;
    nt = band * GN + loc % GN;
}

// ============ fused q/k 3xTF32 split GEMM =================================
// One CTA: A = x (hi/lo) tile 128xK, B = Wq^T and Wk^T (hi/lo) tiles 128xK.
// Outputs q and k 128x128 tiles. 8 warps 4(M)x2(N), warp tile 32x64 per output,
// A fragments shared across both outputs. STAGES=2, 216KB smem.
__global__ __launch_bounds__(256, 1)
void gemm_qk(const float* __restrict__ Ahi, const float* __restrict__ Alo,
             const float* __restrict__ BqH, const float* __restrict__ BqL,
             const float* __restrict__ BkH, const float* __restrict__ BkL,
             float* __restrict__ Q, float* __restrict__ K_out)
{
    constexpr int K = DIM;
    constexpr int STGF = 6 * TILEF;

    extern __shared__ float sm[];
    const uint32_t sbase = smem_u32(sm);

    const int tid  = threadIdx.x;
    const int lane = tid & 31, wid = tid >> 5;
    const int warpM = wid & 3, warpN = wid >> 2;

    int mti, nti;
    swz_tile(blockIdx.x, T_TOK / 128, mti, nti);
    const int m0 = mti * 128, n0 = nti * 128;
    const int KT = K >> 5;

    const float* bases[6] = {
        Ahi + (size_t)m0 * K, Alo + (size_t)m0 * K,
        BqH + (size_t)n0 * K, BqL + (size_t)n0 * K,
        BkH + (size_t)n0 * K, BkL + (size_t)n0 * K };

    auto load_stage = [&](int s, int kt) {
        const uint32_t st = sbase + (uint32_t)s * (STGF * 4);
        #pragma unroll
        for (int tle = 0; tle < 6; ++tle) {
            const float* base = bases[tle] + kt * 32;
            #pragma unroll
            for (int i = 0; i < 4; ++i) {
                const int idx = tid + i * 256;      // 0..1023 within tile
                const int r = idx >> 3, g = idx & 7;
                cp16(st + (uint32_t)(tle * TILEF + r * SK + g * 4) * 4,
                     base + (size_t)r * K + g * 4);
            }
        }
    };

    float accq[2][8][4], acck[2][8][4];
    #pragma unroll
    for (int mt = 0; mt < 2; ++mt)
        #pragma unroll
        for (int nt = 0; nt < 8; ++nt)
            #pragma unroll
            for (int j = 0; j < 4; ++j) { accq[mt][nt][j] = 0.f; acck[mt][nt][j] = 0.f; }

    load_stage(0, 0); cp_commit();

    for (int kt = 0; kt < KT; ++kt) {
        __syncthreads();
        if (kt + 1 < KT) load_stage((kt + 1) & 1, kt + 1);
        cp_commit();
        cp_wait<1>();
        __syncthreads();

        const float* sA  = sm + (kt & 1) * STGF;
        const float* sAl = sA + TILEF;
        const float* sBqH = sA + 2 * TILEF;
        const float* sBqL = sA + 3 * TILEF;
        const float* sBkH = sA + 4 * TILEF;
        const float* sBkL = sA + 5 * TILEF;

        #pragma unroll
        for (int ks = 0; ks < 4; ++ks) {
            const int k0 = ks * 8 + (lane & 3);
            uint32_t aH[2][4], aL[2][4];
            #pragma unroll
            for (int mt = 0; mt < 2; ++mt) {
                const int r = warpM * 32 + mt * 16 + (lane >> 2);
                aH[mt][0] = __float_as_uint(sA[r * SK + k0]);
                aH[mt][1] = __float_as_uint(sA[(r + 8) * SK + k0]);
                aH[mt][2] = __float_as_uint(sA[r * SK + k0 + 4]);
                aH[mt][3] = __float_as_uint(sA[(r + 8) * SK + k0 + 4]);
                aL[mt][0] = __float_as_uint(sAl[r * SK + k0]);
                aL[mt][1] = __float_as_uint(sAl[(r + 8) * SK + k0]);
                aL[mt][2] = __float_as_uint(sAl[r * SK + k0 + 4]);
                aL[mt][3] = __float_as_uint(sAl[(r + 8) * SK + k0 + 4]);
            }
            #pragma unroll
            for (int nt = 0; nt < 8; ++nt) {
                const int n = warpN * 64 + nt * 8 + (lane >> 2);
                const int o0 = n * SK + k0, o1 = n * SK + k0 + 4;
                {   // q output
                    const uint32_t bH0 = __float_as_uint(sBqH[o0]);
                    const uint32_t bH1 = __float_as_uint(sBqH[o1]);
                    const uint32_t bL0 = __float_as_uint(sBqL[o0]);
                    const uint32_t bL1 = __float_as_uint(sBqL[o1]);
                    #pragma unroll
                    for (int mt = 0; mt < 2; ++mt) {
                        MMA8(accq[mt][nt], aH[mt], bH0, bH1);
                        MMA8(accq[mt][nt], aL[mt], bH0, bH1);
                        MMA8(accq[mt][nt], aH[mt], bL0, bL1);
                    }
                }
                {   // k output
                    const uint32_t bH0 = __float_as_uint(sBkH[o0]);
                    const uint32_t bH1 = __float_as_uint(sBkH[o1]);
                    const uint32_t bL0 = __float_as_uint(sBkL[o0]);
                    const uint32_t bL1 = __float_as_uint(sBkL[o1]);
                    #pragma unroll
                    for (int mt = 0; mt < 2; ++mt) {
                        MMA8(acck[mt][nt], aH[mt], bH0, bH1);
                        MMA8(acck[mt][nt], aL[mt], bH0, bH1);
                        MMA8(acck[mt][nt], aH[mt], bL0, bL1);
                    }
                }
            }
        }
    }

    #pragma unroll
    for (int mt = 0; mt < 2; ++mt) {
        const int r = m0 + warpM * 32 + mt * 16 + (lane >> 2);
        #pragma unroll
        for (int nt = 0; nt < 8; ++nt) {
            const int c = n0 + warpN * 64 + nt * 8 + ((lane & 3) << 1);
            const size_t o0 = (size_t)r * DIM + c;
            const size_t o1 = (size_t)(r + 8) * DIM + c;
            *(float2*)(Q + o0)     = make_float2(accq[mt][nt][0], accq[mt][nt][1]);
            *(float2*)(Q + o1)     = make_float2(accq[mt][nt][2], accq[mt][nt][3]);
            *(float2*)(K_out + o0) = make_float2(acck[mt][nt][0], acck[mt][nt][1]);
            *(float2*)(K_out + o1) = make_float2(acck[mt][nt][2], acck[mt][nt][3]);
        }
    }
}

// ============ 256-row GEMM: plain (fc2+res) or fused SwiGLU (fc1) =========
// BM=256. GLU=false: BN=128, C = A@Bt^T + res.
// GLU=true: per-half BN=64; B rows [n0,n0+64) (hh) and [HID+n0,+64) (g);
// writes s = tf32(silu(g)*hh), N=HID. 8 warps 4(M)x2(N).
template<bool GLU, int STAGES>
__global__ __launch_bounds__(256, 1)
void gemm2(const float* __restrict__ A, const float* __restrict__ Bt,
           const float* __restrict__ res, float* __restrict__ C,
           int N, int K, int tiles_m)
{
    constexpr int NH = GLU ? 2 : 1;
    constexpr int NT = GLU ? 4 : 8;

    extern __shared__ float sm[];
    const uint32_t sbase = smem_u32(sm);

    const int tid  = threadIdx.x;
    const int lane = tid & 31, wid = tid >> 5;
    const int warpM = wid & 3, warpN = wid >> 2;

    int mti, nti;
    swz_tile(blockIdx.x, tiles_m, mti, nti);
    const int m0 = mti * 256;
    const int n0 = nti * (GLU ? 64 : 128);
    const int KT = K >> 5;

    auto load_stage = [&](int s, int kt) {
        const uint32_t st = sbase + (uint32_t)s * (STGF2 * 4);
        #pragma unroll
        for (int it = 0; it < 12; ++it) {
            const int idx = tid + it * 256;
            const int r = idx >> 3, g = idx & 7;
            const uint32_t d = st + (uint32_t)(r * SK + g * 4) * 4;
            const float* src;
            if (it < 8) {
                src = A + (size_t)(m0 + r) * K + kt * 32 + g * 4;
            } else {
                const int rb = r - 256;
                const int brow = GLU ? ((rb < 64) ? (n0 + rb) : (HID + n0 + rb - 64))
                                     : (n0 + rb);
                src = Bt + (size_t)brow * K + kt * 32 + g * 4;
            }
            cp16(d, src);
        }
    };

    float acc[NH][4][NT][4];
    #pragma unroll
    for (int h = 0; h < NH; ++h)
        #pragma unroll
        for (int mt = 0; mt < 4; ++mt)
            #pragma unroll
            for (int nt = 0; nt < NT; ++nt)
                #pragma unroll
                for (int j = 0; j < 4; ++j) acc[h][mt][nt][j] = 0.f;

    #pragma unroll
    for (int s = 0; s < STAGES - 1; ++s) { load_stage(s, s); cp_commit(); }

    for (int kt = 0; kt < KT; ++kt) {
        __syncthreads();
        const int lkt = kt + STAGES - 1;
        if (lkt < KT) load_stage(lkt % STAGES, lkt);
        cp_commit();
        cp_wait<STAGES - 1>();
        __syncthreads();

        const float* sA = sm + (kt % STAGES) * STGF2;
        const float* sB = sA + 256 * SK;

        #pragma unroll
        for (int ks = 0; ks < 4; ++ks) {
            const int k0 = ks * 8 + (lane & 3);
            uint32_t af[4][4];
            #pragma unroll
            for (int mt = 0; mt < 4; ++mt) {
                const int r = warpM * 64 + mt * 16 + (lane >> 2);
                af[mt][0] = __float_as_uint(sA[r * SK + k0]);
                af[mt][1] = __float_as_uint(sA[(r + 8) * SK + k0]);
                af[mt][2] = __float_as_uint(sA[r * SK + k0 + 4]);
                af[mt][3] = __float_as_uint(sA[(r + 8) * SK + k0 + 4]);
            }
            #pragma unroll
            for (int h = 0; h < NH; ++h) {
                #pragma unroll
                for (int nt = 0; nt < NT; ++nt) {
                    const int n = (GLU ? (h * 64 + warpN * 32) : (warpN * 64))
                                + nt * 8 + (lane >> 2);
                    const uint32_t b0 = __float_as_uint(sB[n * SK + k0]);
                    const uint32_t b1 = __float_as_uint(sB[n * SK + k0 + 4]);
                    #pragma unroll
                    for (int mt = 0; mt < 4; ++mt)
                        MMA8(acc[h][mt][nt], af[mt], b0, b1);
                }
            }
        }
    }

    #pragma unroll
    for (int mt = 0; mt < 4; ++mt) {
        const int r = m0 + warpM * 64 + mt * 16 + (lane >> 2);
        #pragma unroll
        for (int nt = 0; nt < NT; ++nt) {
            const int c = n0 + (GLU ? warpN * 32 : warpN * 64)
                        + nt * 8 + ((lane & 3) << 1);
            if (GLU) {
                #pragma unroll
                for (int j = 0; j < 2; ++j) {
                    const size_t o = (size_t)(r + j * 8) * N + c;
                    const float hh0 = acc[0][mt][nt][2 * j];
                    const float hh1 = acc[0][mt][nt][2 * j + 1];
                    const float gg0 = acc[1][mt][nt][2 * j];
                    const float gg1 = acc[1][mt][nt][2 * j + 1];
                    float2 v;
                    v.x = tf32_rna(hh0 * (gg0 / (1.f + expf(-gg0))));
                    v.y = tf32_rna(hh1 * (gg1 / (1.f + expf(-gg1))));
                    *(float2*)(C + o) = v;
                }
            } else {
                float2 v0 = make_float2(acc[0][mt][nt][0], acc[0][mt][nt][1]);
                float2 v1 = make_float2(acc[0][mt][nt][2], acc[0][mt][nt][3]);
                const size_t o0 = (size_t)r * N + c;
                const size_t o1 = (size_t)(r + 8) * N + c;
                if (res) {
                    const float2 d0 = *(const float2*)(res + o0);
                    const float2 d1 = *(const float2*)(res + o1);
                    v0.x += d0.x; v0.y += d0.y;
                    v1.x += d1.x; v1.y += d1.y;
                }
                *(float2*)(C + o0) = v0;
                *(float2*)(C + o1) = v1;
            }
        }
    }
}

// ---------------- pre-passes ----------------
__global__ void split_kernel(const float* __restrict__ x,
                             float* __restrict__ hi, float* __restrict__ lo)
{
    const size_t i = (size_t)blockIdx.x * blockDim.x + threadIdx.x;
    if (i >= (size_t)T_TOK * DIM) return;
    const float v = x[i];
    const float h = tf32_rna(v);
    hi[i] = h;
    lo[i] = tf32_rna(v - h);
}

__global__ void transpose_rna(const float* __restrict__ W, float* __restrict__ Wt,
                              int K, int N)
{
    __shared__ float t[32][33];
    const int n0 = blockIdx.x * 32, k0 = blockIdx.y * 32;
    for (int i = threadIdx.y; i < 32; i += 8)
        t[i][threadIdx.x] = W[(size_t)(k0 + i) * N + n0 + threadIdx.x];
    __syncthreads();
    for (int i = threadIdx.y; i < 32; i += 8)
        Wt[(size_t)(n0 + i) * K + k0 + threadIdx.x] = tf32_rna(t[threadIdx.x][i]);
}

__global__ void transpose_split(const float* __restrict__ W,
                                float* __restrict__ WtH, float* __restrict__ WtL,
                                int K, int N)
{
    __shared__ float t[32][33];
    const int n0 = blockIdx.x * 32, k0 = blockIdx.y * 32;
    for (int i = threadIdx.y; i < 32; i += 8)
        t[i][threadIdx.x] = W[(size_t)(k0 + i) * N + n0 + threadIdx.x];
    __syncthreads();
    for (int i = threadIdx.y; i < 32; i += 8) {
        const float v = t[threadIdx.x][i];
        const float h = tf32_rna(v);
        const size_t o = (size_t)(n0 + i) * K + k0 + threadIdx.x;
        WtH[o] = h;
        WtL[o] = tf32_rna(v - h);
    }
}

// ---------------- block reduction helper ----------------
__device__ __forceinline__ float block_sum(float v, float* sm)
{
    #pragma unroll
    for (int o = 16; o > 0; o >>= 1) v += __shfl_down_sync(0xffffffffu, v, o);
    const int lane = threadIdx.x & 31, wid = threadIdx.x >> 5;
    if (lane == 0) sm[wid] = v;
    __syncthreads();
    v = (threadIdx.x < (blockDim.x >> 5)) ? sm[threadIdx.x] : 0.f;
    if (wid == 0) {
        #pragma unroll
        for (int o = 16; o > 0; o >>= 1) v += __shfl_down_sync(0xffffffffu, v, o);
    }
    return v;
}

// ---------------- rmsnorm (emits rna-tf32 values) ----------------
__global__ void rmsnorm_kernel(const float* __restrict__ x,
                               const float* __restrict__ w,
                               float* __restrict__ xn)
{
    __shared__ float sm[32];
    __shared__ float s_inv;
    const int row = blockIdx.x;
    const float* xr = x + (size_t)row * DIM;
    float ss = 0.f;
    for (int i = threadIdx.x; i < DIM; i += blockDim.x) {
        const float v = xr[i];
        ss = fmaf(v, v, ss);
    }
    ss = block_sum(ss, sm);
    if (threadIdx.x == 0) s_inv = rsqrtf(ss / (float)DIM + RMS_EPS);
    __syncthreads();
    const float inv = s_inv;
    float* xo = xn + (size_t)row * DIM;
    for (int i = threadIdx.x; i < DIM; i += blockDim.x)
        xo[i] = tf32_rna(xr[i] * inv * w[i]);
}

// ------- per-token stats: |q_t|^2, |k_t|^2, q_{t-1}.k_t -------------------
__global__ void qkstats_kernel(const float* __restrict__ q,
                               const float* __restrict__ k,
                               float* __restrict__ nq2,
                               float* __restrict__ nk2,
                               float* __restrict__ dqk)
{
    __shared__ float sm[32];
    const int t = blockIdx.x;
    const float* qr = q + (size_t)t * DIM;
    const float* kr = k + (size_t)t * DIM;
    float sq = 0.f, sk = 0.f, sd = 0.f;
    for (int i = threadIdx.x; i < DIM; i += blockDim.x) {
        const float qv = qr[i], kv = kr[i];
        sq = fmaf(qv, qv, sq);
        sk = fmaf(kv, kv, sk);
        if (t > 0) sd = fmaf(qr[i - DIM], kv, sd);
    }
    sq = block_sum(sq, sm);
    __syncthreads();
    sk = block_sum(sk, sm);
    __syncthreads();
    sd = block_sum(sd, sm);
    if (threadIdx.x == 0) {
        nq2[t] = sq;
        nk2[t] = sk;
        dqk[t] = (t > 0) ? sd : 0.f;
    }
}

// ------- boundary probs -> scan coefficients a_t, c_t ---------------------
__global__ void pcoef_kernel(const float* __restrict__ nq2,
                             const float* __restrict__ nk2,
                             const float* __restrict__ dqk,
                             const int* __restrict__ cu, int nseq,
                             float* __restrict__ a, float* __restrict__ c)
{
    const int t = blockIdx.x * blockDim.x + threadIdx.x;
    if (t >= T_TOK) return;
    bool ss = false;
    for (int i = 0; i < nseq; ++i) ss |= (cu[i] == t);
    float p;
    if (t == 0 || ss) {
        p = 1.0f;
    } else {
        const float cosv = dqk[t] * rsqrtf(nq2[t - 1] * nk2[t]);
        p = (1.0f - cosv) * 0.5f;
    }
    p = fminf(fmaxf(p, EPS_P), 1.0f - EPS_P);
    const bool b = (p >= 0.5f);
    a[t] = (ss || t == 0) ? 0.f : (b ? 1.f - p : 1.f);
    c[t] = b ? p : 0.f;
}

// ------- segmented EMA scan: h_t = a_t h_{t-1} + c_t z_t ------------------
__global__ void ema_scan_kernel(const float* __restrict__ z,
                                const float* __restrict__ a,
                                const float* __restrict__ c,
                                const int* __restrict__ cu,
                                float* __restrict__ out)
{
    __shared__ float sa[1024];
    __shared__ float sc[1024];
    const int seg = blockIdx.y;
    const int t0 = cu[seg], t1 = cu[seg + 1];
    const int ch = blockIdx.x * blockDim.x + threadIdx.x;
    float h = 0.f;
    for (int base = t0; base < t1; base += 1024) {
        const int len = min(1024, t1 - base);
        __syncthreads();
        for (int i = threadIdx.x; i < len; i += blockDim.x) {
            sa[i] = a[base + i];
            sc[i] = c[base + i];
        }
        __syncthreads();
        for (int i = 0; i < len; ++i) {
            const size_t off = (size_t)(base + i) * DIM + ch;
            const float zv = z[off];
            h = fmaf(sa[i], h, sc[i] * zv);
            out[off] = h;
        }
    }
}

// ---------------- launch ----------------
extern "C" void kernel_launch(void* const* d_in, const int* in_sizes, int n_in,
                              void* d_out, int out_size)
{
    const float* x      = (const float*)d_in[0];
    const float* Wq     = (const float*)d_in[1];
    const float* Wk     = (const float*)d_in[2];
    const float* fc1    = (const float*)d_in[3];
    const float* fc2    = (const float*)d_in[4];
    const float* norm_w = (const float*)d_in[5];
    const int*   cu     = (const int*)d_in[6];
    float*       out    = (float*)d_out;
    const int nseq = in_sizes[6] - 1;

    float *xhi, *xlo, *wqth, *wqtl, *wkth, *wktl, *fc1t, *fc2t;
    float *q, *k, *xn, *s, *z, *nq, *nk, *dqk, *a, *c;
    cudaGetSymbolAddress((void**)&xhi,  g_xhi);
    cudaGetSymbolAddress((void**)&xlo,  g_xlo);
    cudaGetSymbolAddress((void**)&wqth, g_wqth);
    cudaGetSymbolAddress((void**)&wqtl, g_wqtl);
    cudaGetSymbolAddress((void**)&wkth, g_wkth);
    cudaGetSymbolAddress((void**)&wktl, g_wktl);
    cudaGetSymbolAddress((void**)&fc1t, g_fc1t);
    cudaGetSymbolAddress((void**)&fc2t, g_fc2t);
    cudaGetSymbolAddress((void**)&q,    g_q);
    cudaGetSymbolAddress((void**)&k,    g_k);
    cudaGetSymbolAddress((void**)&xn,   g_xn);
    cudaGetSymbolAddress((void**)&s,    g_s);
    cudaGetSymbolAddress((void**)&z,    g_z);
    cudaGetSymbolAddress((void**)&nq,   g_nq);
    cudaGetSymbolAddress((void**)&nk,   g_nk);
    cudaGetSymbolAddress((void**)&dqk,  g_dqk);
    cudaGetSymbolAddress((void**)&a,    g_a);
    cudaGetSymbolAddress((void**)&c,    g_c);

    const int SMEM_QK = 2 * 6 * TILEF * 4;   // 221184 B (2 stages x 6 tiles)
    const int SMEM_G2 = 3 * STGF2 * 4;       // 165888 B
    cudaFuncSetAttribute(gemm_qk,
                         cudaFuncAttributeMaxDynamicSharedMemorySize, SMEM_QK);
    cudaFuncSetAttribute(gemm2<true, 3>,
                         cudaFuncAttributeMaxDynamicSharedMemorySize, SMEM_G2);
    cudaFuncSetAttribute(gemm2<false, 3>,
                         cudaFuncAttributeMaxDynamicSharedMemorySize, SMEM_G2);

    // ---- pre-passes: splits + transposed tf32 weights ----
    {
        const size_t n = (size_t)T_TOK * DIM;
        split_kernel<<<(unsigned)((n + 255) / 256), 256>>>(x, xhi, xlo);
    }
    transpose_split<<<dim3(DIM / 32, DIM / 32), dim3(32, 8)>>>(Wq, wqth, wqtl, DIM, DIM);
    transpose_split<<<dim3(DIM / 32, DIM / 32), dim3(32, 8)>>>(Wk, wkth, wktl, DIM, DIM);
    transpose_rna<<<dim3(2 * HID / 32, DIM / 32), dim3(32, 8)>>>(fc1, fc1t, DIM, 2 * HID);
    transpose_rna<<<dim3(DIM / 32, HID / 32), dim3(32, 8)>>>(fc2, fc2t, HID, DIM);

    // ---- fused q+k via 3xTF32 split GEMM (sign-critical path) ----
    gemm_qk<<<(T_TOK / 128) * (DIM / 128), 256, SMEM_QK>>>(
        xhi, xlo, wqth, wqtl, wkth, wktl, q, k);

    // boundary statistics and scan coefficients
    qkstats_kernel<<<T_TOK, 256>>>(q, k, nq, nk, dqk);
    pcoef_kernel<<<T_TOK / 256, 256>>>(nq, nk, dqk, cu, nseq, a, c);

    // xn = rmsnorm(x)  (tf32-rounded)
    rmsnorm_kernel<<<T_TOK, 256>>>(x, norm_w, xn);

    // s = silu(xn@fc1_g) * (xn@fc1_h)   -- fused fc1 + SwiGLU
    gemm2<true, 3><<<(T_TOK / 256) * (HID / 64), 256, SMEM_G2>>>(
        xn, fc1t, nullptr, s, HID, DIM, T_TOK / 256);

    // z = x + s @ fc2
    gemm2<false, 3><<<(T_TOK / 256) * (DIM / 128), 256, SMEM_G2>>>(
        s, fc2t, x, z, DIM, HID, T_TOK / 256);

    // segmented EMA scan -> out
    ema_scan_kernel<<<dim3(DIM / 256, nseq), 256>>>(z, a, c, cu, out);
}

// round 13
// speedup vs baseline: 1.5108x; 1.5108x over previous
#include <cuda_runtime.h>
#include <cuda_bf16.h>
#include <math.h>
#include <stdint.h>

// ---------------- problem constants (fixed-shape problem) ----------------
#define T_TOK 8192
#define DIM   2048
#define HID   8192
#define EPS_P 1e-4f
#define RMS_EPS 1e-5f

// smem tile geometry: rows x 32 tf32, row stride 36 floats (conflict-free)
#define SK    36
#define TILEF 4608    // 128*36 floats per 128-row operand tile
#define STGF2 13824   // 384*36 floats per stage (256-row A + 128-row B)
#define GN    16      // band width (n-tiles) for the L2 swizzle

// ---------------- scratch (static device globals; no allocs) -------------
__device__ float g_xhi [(size_t)T_TOK * DIM];
__device__ float g_xlo [(size_t)T_TOK * DIM];
__device__ float g_wqth[(size_t)DIM * DIM];
__device__ float g_wqtl[(size_t)DIM * DIM];
__device__ float g_wkth[(size_t)DIM * DIM];
__device__ float g_wktl[(size_t)DIM * DIM];
__device__ float g_fc1t[(size_t)2 * HID * DIM];
__device__ float g_fc2t[(size_t)DIM * HID];
__device__ float g_q  [(size_t)T_TOK * DIM];
__device__ float g_k  [(size_t)T_TOK * DIM];
__device__ float g_xn [(size_t)T_TOK * DIM];
__device__ float g_s  [(size_t)T_TOK * HID];
__device__ float g_z  [(size_t)T_TOK * DIM];
__device__ float g_nq [T_TOK];
__device__ float g_nk [T_TOK];
__device__ float g_dqk[T_TOK];
__device__ float g_a  [T_TOK];
__device__ float g_c  [T_TOK];

// ---------------- PTX helpers ----------------
__device__ __forceinline__ uint32_t smem_u32(const void* p) {
    uint32_t a;
    asm("{ .reg .u64 t; cvta.to.shared.u64 t, %1; cvt.u32.u64 %0, t; }" : "=r"(a) : "l"(p));
    return a;
}
__device__ __forceinline__ float tf32_rna(float v) {
    uint32_t r;
    asm("cvt.rna.tf32.f32 %0, %1;" : "=r"(r) : "f"(v));
    return __uint_as_float(r);
}
__device__ __forceinline__ void cp16(uint32_t dst, const float* src) {
    asm volatile("cp.async.cg.shared.global [%0], [%1], 16;" :: "r"(dst), "l"(src) : "memory");
}
__device__ __forceinline__ void cp_commit() {
    asm volatile("cp.async.commit_group;" ::: "memory");
}
template<int N> __device__ __forceinline__ void cp_wait() {
    asm volatile("cp.async.wait_group %0;" :: "n"(N) : "memory");
}

// m16n8k8 row.col tf32 MMA: D += A*B, fp32 accumulate
#define MMA8(c, a, b0, b1)                                                      \
    asm volatile(                                                               \
        "mma.sync.aligned.m16n8k8.row.col.f32.tf32.tf32.f32 "                   \
        "{%0,%1,%2,%3}, {%4,%5,%6,%7}, {%8,%9}, {%0,%1,%2,%3};"                 \
        : "+f"((c)[0]), "+f"((c)[1]), "+f"((c)[2]), "+f"((c)[3])                \
        : "r"((a)[0]), "r"((a)[1]), "r"((a)[2]), "r"((a)[3]),                   \
          "r"(b0), "r"(b1))

// band swizzle: 1D grid -> (m_tile, n_tile); m fastest inside a GN-wide band
__device__ __forceinline__ void swz_tile(int bid, int tiles_m, int& mt, int& nt) {
    const int per_band = GN * tiles_m;
    const int band = bid / per_band;
    const int loc  = bid % per_band;
    mt = loc / GN;
    nt = band * GN + loc % GN;
}

// ================= 128x128 3xTF32 split GEMM (q/k path) ===================
// R10-proven kernel; only the tile indexing switched to the band swizzle.
template<bool SPLIT, int STAGES>
__global__ __launch_bounds__(256, 1)
void gemm_mma(const float* __restrict__ A,  const float* __restrict__ A2,
              const float* __restrict__ Bt, const float* __restrict__ Bt2,
              const float* __restrict__ res, float* __restrict__ C,
              int N, int K, int tiles_m)
{
    constexpr int NOP  = SPLIT ? 2 : 1;
    constexpr int STGF = 2 * NOP * TILEF;

    extern __shared__ float sm[];
    const uint32_t sbase = smem_u32(sm);

    const int tid  = threadIdx.x;
    const int lane = tid & 31, wid = tid >> 5;
    const int warpM = wid & 3, warpN = wid >> 2;

    int mti, nti;
    swz_tile(blockIdx.x, tiles_m, mti, nti);
    const int m0 = mti * 128, n0 = nti * 128;
    const int KT = K >> 5;

    const float* Ab  = A  + (size_t)m0 * K;
    const float* Bb  = Bt + (size_t)n0 * K;
    const float* A2b = SPLIT ? A2  + (size_t)m0 * K : nullptr;
    const float* B2b = SPLIT ? Bt2 + (size_t)n0 * K : nullptr;

    auto load_stage = [&](int s, int kt) {
        const uint32_t st = sbase + (uint32_t)s * (STGF * 4);
        const float* a = Ab + kt * 32;
        const float* b = Bb + kt * 32;
        #pragma unroll
        for (int it = 0; it < 4; ++it) {
            const int idx = tid + it * 256;
            const int r = idx >> 3, g = idx & 7;
            const uint32_t d = (uint32_t)(r * SK + g * 4) * 4;
            const size_t go = (size_t)r * K + g * 4;
            cp16(st + d, a + go);
            cp16(st + (uint32_t)(NOP * TILEF * 4) + d, b + go);
            if (SPLIT) {
                cp16(st + (uint32_t)(TILEF * 4) + d, A2b + kt * 32 + go);
                cp16(st + (uint32_t)(3 * TILEF * 4) + d, B2b + kt * 32 + go);
            }
        }
    };

    float acc[2][8][4];
    #pragma unroll
    for (int mt = 0; mt < 2; ++mt)
        #pragma unroll
        for (int nt = 0; nt < 8; ++nt)
            #pragma unroll
            for (int j = 0; j < 4; ++j) acc[mt][nt][j] = 0.f;

    #pragma unroll
    for (int s = 0; s < STAGES - 1; ++s) { load_stage(s, s); cp_commit(); }

    for (int kt = 0; kt < KT; ++kt) {
        __syncthreads();
        const int lkt = kt + STAGES - 1;
        if (lkt < KT) load_stage(lkt % STAGES, lkt);
        cp_commit();
        cp_wait<STAGES - 1>();
        __syncthreads();

        const float* sA  = sm + (kt % STAGES) * STGF;
        const float* sAl = sA + TILEF;
        const float* sB  = sA + NOP * TILEF;
        const float* sBl = sB + TILEF;

        #pragma unroll
        for (int ks = 0; ks < 4; ++ks) {
            const int k0 = ks * 8 + (lane & 3);
            uint32_t aH[2][4], aL[2][4];
            #pragma unroll
            for (int mt = 0; mt < 2; ++mt) {
                const int r = warpM * 32 + mt * 16 + (lane >> 2);
                aH[mt][0] = __float_as_uint(sA[r * SK + k0]);
                aH[mt][1] = __float_as_uint(sA[(r + 8) * SK + k0]);
                aH[mt][2] = __float_as_uint(sA[r * SK + k0 + 4]);
                aH[mt][3] = __float_as_uint(sA[(r + 8) * SK + k0 + 4]);
                if (SPLIT) {
                    aL[mt][0] = __float_as_uint(sAl[r * SK + k0]);
                    aL[mt][1] = __float_as_uint(sAl[(r + 8) * SK + k0]);
                    aL[mt][2] = __float_as_uint(sAl[r * SK + k0 + 4]);
                    aL[mt][3] = __float_as_uint(sAl[(r + 8) * SK + k0 + 4]);
                }
            }
            #pragma unroll
            for (int nt = 0; nt < 8; ++nt) {
                const int n = warpN * 64 + nt * 8 + (lane >> 2);
                const uint32_t bH0 = __float_as_uint(sB[n * SK + k0]);
                const uint32_t bH1 = __float_as_uint(sB[n * SK + k0 + 4]);
                #pragma unroll
                for (int mt = 0; mt < 2; ++mt) MMA8(acc[mt][nt], aH[mt], bH0, bH1);
                if (SPLIT) {
                    const uint32_t bL0 = __float_as_uint(sBl[n * SK + k0]);
                    const uint32_t bL1 = __float_as_uint(sBl[n * SK + k0 + 4]);
                    #pragma unroll
                    for (int mt = 0; mt < 2; ++mt) {
                        MMA8(acc[mt][nt], aL[mt], bH0, bH1);
                        MMA8(acc[mt][nt], aH[mt], bL0, bL1);
                    }
                }
            }
        }
    }

    #pragma unroll
    for (int mt = 0; mt < 2; ++mt) {
        const int r = m0 + warpM * 32 + mt * 16 + (lane >> 2);
        #pragma unroll
        for (int nt = 0; nt < 8; ++nt) {
            const int c = n0 + warpN * 64 + nt * 8 + ((lane & 3) << 1);
            float2 v0 = make_float2(acc[mt][nt][0], acc[mt][nt][1]);
            float2 v1 = make_float2(acc[mt][nt][2], acc[mt][nt][3]);
            const size_t o0 = (size_t)r * N + c;
            const size_t o1 = (size_t)(r + 8) * N + c;
            if (res) {
                const float2 d0 = *(const float2*)(res + o0);
                const float2 d1 = *(const float2*)(res + o1);
                v0.x += d0.x; v0.y += d0.y;
                v1.x += d1.x; v1.y += d1.y;
            }
            *(float2*)(C + o0) = v0;
            *(float2*)(C + o1) = v1;
        }
    }
}

// ============ 256-row GEMM: plain (fc2+res) or fused SwiGLU (fc1) =========
// BM=256. GLU=false: BN=128, C = A@Bt^T + res.
// GLU=true: per-half BN=64; B rows [n0,n0+64) (hh) and [HID+n0,+64) (g);
// writes s = tf32(silu(g)*hh), N=HID. 8 warps 4(M)x2(N).
template<bool GLU, int STAGES>
__global__ __launch_bounds__(256, 1)
void gemm2(const float* __restrict__ A, const float* __restrict__ Bt,
           const float* __restrict__ res, float* __restrict__ C,
           int N, int K, int tiles_m)
{
    constexpr int NH = GLU ? 2 : 1;
    constexpr int NT = GLU ? 4 : 8;

    extern __shared__ float sm[];
    const uint32_t sbase = smem_u32(sm);

    const int tid  = threadIdx.x;
    const int lane = tid & 31, wid = tid >> 5;
    const int warpM = wid & 3, warpN = wid >> 2;

    int mti, nti;
    swz_tile(blockIdx.x, tiles_m, mti, nti);
    const int m0 = mti * 256;
    const int n0 = nti * (GLU ? 64 : 128);
    const int KT = K >> 5;

    auto load_stage = [&](int s, int kt) {
        const uint32_t st = sbase + (uint32_t)s * (STGF2 * 4);
        #pragma unroll
        for (int it = 0; it < 12; ++it) {
            const int idx = tid + it * 256;
            const int r = idx >> 3, g = idx & 7;
            const uint32_t d = st + (uint32_t)(r * SK + g * 4) * 4;
            const float* src;
            if (it < 8) {
                src = A + (size_t)(m0 + r) * K + kt * 32 + g * 4;
            } else {
                const int rb = r - 256;
                const int brow = GLU ? ((rb < 64) ? (n0 + rb) : (HID + n0 + rb - 64))
                                     : (n0 + rb);
                src = Bt + (size_t)brow * K + kt * 32 + g * 4;
            }
            cp16(d, src);
        }
    };

    float acc[NH][4][NT][4];
    #pragma unroll
    for (int h = 0; h < NH; ++h)
        #pragma unroll
        for (int mt = 0; mt < 4; ++mt)
            #pragma unroll
            for (int nt = 0; nt < NT; ++nt)
                #pragma unroll
                for (int j = 0; j < 4; ++j) acc[h][mt][nt][j] = 0.f;

    #pragma unroll
    for (int s = 0; s < STAGES - 1; ++s) { load_stage(s, s); cp_commit(); }

    for (int kt = 0; kt < KT; ++kt) {
        __syncthreads();
        const int lkt = kt + STAGES - 1;
        if (lkt < KT) load_stage(lkt % STAGES, lkt);
        cp_commit();
        cp_wait<STAGES - 1>();
        __syncthreads();

        const float* sA = sm + (kt % STAGES) * STGF2;
        const float* sB = sA + 256 * SK;

        #pragma unroll
        for (int ks = 0; ks < 4; ++ks) {
            const int k0 = ks * 8 + (lane & 3);
            uint32_t af[4][4];
            #pragma unroll
            for (int mt = 0; mt < 4; ++mt) {
                const int r = warpM * 64 + mt * 16 + (lane >> 2);
                af[mt][0] = __float_as_uint(sA[r * SK + k0]);
                af[mt][1] = __float_as_uint(sA[(r + 8) * SK + k0]);
                af[mt][2] = __float_as_uint(sA[r * SK + k0 + 4]);
                af[mt][3] = __float_as_uint(sA[(r + 8) * SK + k0 + 4]);
            }
            #pragma unroll
            for (int h = 0; h < NH; ++h) {
                #pragma unroll
                for (int nt = 0; nt < NT; ++nt) {
                    const int n = (GLU ? (h * 64 + warpN * 32) : (warpN * 64))
                                + nt * 8 + (lane >> 2);
                    const uint32_t b0 = __float_as_uint(sB[n * SK + k0]);
                    const uint32_t b1 = __float_as_uint(sB[n * SK + k0 + 4]);
                    #pragma unroll
                    for (int mt = 0; mt < 4; ++mt)
                        MMA8(acc[h][mt][nt], af[mt], b0, b1);
                }
            }
        }
    }

    #pragma unroll
    for (int mt = 0; mt < 4; ++mt) {
        const int r = m0 + warpM * 64 + mt * 16 + (lane >> 2);
        #pragma unroll
        for (int nt = 0; nt < NT; ++nt) {
            const int c = n0 + (GLU ? warpN * 32 : warpN * 64)
                        + nt * 8 + ((lane & 3) << 1);
            if (GLU) {
                #pragma unroll
                for (int j = 0; j < 2; ++j) {
                    const size_t o = (size_t)(r + j * 8) * N + c;
                    const float hh0 = acc[0][mt][nt][2 * j];
                    const float hh1 = acc[0][mt][nt][2 * j + 1];
                    const float gg0 = acc[1][mt][nt][2 * j];
                    const float gg1 = acc[1][mt][nt][2 * j + 1];
                    float2 v;
                    v.x = tf32_rna(hh0 * (gg0 / (1.f + expf(-gg0))));
                    v.y = tf32_rna(hh1 * (gg1 / (1.f + expf(-gg1))));
                    *(float2*)(C + o) = v;
                }
            } else {
                float2 v0 = make_float2(acc[0][mt][nt][0], acc[0][mt][nt][1]);
                float2 v1 = make_float2(acc[0][mt][nt][2], acc[0][mt][nt][3]);
                const size_t o0 = (size_t)r * N + c;
                const size_t o1 = (size_t)(r + 8) * N + c;
                if (res) {
                    const float2 d0 = *(const float2*)(res + o0);
                    const float2 d1 = *(const float2*)(res + o1);
                    v0.x += d0.x; v0.y += d0.y;
                    v1.x += d1.x; v1.y += d1.y;
                }
                *(float2*)(C + o0) = v0;
                *(float2*)(C + o1) = v1;
            }
        }
    }
}

// ---------------- pre-passes ----------------
__global__ void split_kernel(const float* __restrict__ x,
                             float* __restrict__ hi, float* __restrict__ lo)
{
    const size_t i = (size_t)blockIdx.x * blockDim.x + threadIdx.x;
    if (i >= (size_t)T_TOK * DIM) return;
    const float v = x[i];
    const float h = tf32_rna(v);
    hi[i] = h;
    lo[i] = tf32_rna(v - h);
}

__global__ void transpose_rna(const float* __restrict__ W, float* __restrict__ Wt,
                              int K, int N)
{
    __shared__ float t[32][33];
    const int n0 = blockIdx.x * 32, k0 = blockIdx.y * 32;
    for (int i = threadIdx.y; i < 32; i += 8)
        t[i][threadIdx.x] = W[(size_t)(k0 + i) * N + n0 + threadIdx.x];
    __syncthreads();
    for (int i = threadIdx.y; i < 32; i += 8)
        Wt[(size_t)(n0 + i) * K + k0 + threadIdx.x] = tf32_rna(t[threadIdx.x][i]);
}

__global__ void transpose_split(const float* __restrict__ W,
                                float* __restrict__ WtH, float* __restrict__ WtL,
                                int K, int N)
{
    __shared__ float t[32][33];
    const int n0 = blockIdx.x * 32, k0 = blockIdx.y * 32;
    for (int i = threadIdx.y; i < 32; i += 8)
        t[i][threadIdx.x] = W[(size_t)(k0 + i) * N + n0 + threadIdx.x];
    __syncthreads();
    for (int i = threadIdx.y; i < 32; i += 8) {
        const float v = t[threadIdx.x][i];
        const float h = tf32_rna(v);
        const size_t o = (size_t)(n0 + i) * K + k0 + threadIdx.x;
        WtH[o] = h;
        WtL[o] = tf32_rna(v - h);
    }
}

// ---------------- block reduction helper ----------------
__device__ __forceinline__ float block_sum(float v, float* sm)
{
    #pragma unroll
    for (int o = 16; o > 0; o >>= 1) v += __shfl_down_sync(0xffffffffu, v, o);
    const int lane = threadIdx.x & 31, wid = threadIdx.x >> 5;
    if (lane == 0) sm[wid] = v;
    __syncthreads();
    v = (threadIdx.x < (blockDim.x >> 5)) ? sm[threadIdx.x] : 0.f;
    if (wid == 0) {
        #pragma unroll
        for (int o = 16; o > 0; o >>= 1) v += __shfl_down_sync(0xffffffffu, v, o);
    }
    return v;
}

// ---------------- rmsnorm (emits rna-tf32 values) ----------------
__global__ void rmsnorm_kernel(const float* __restrict__ x,
                               const float* __restrict__ w,
                               float* __restrict__ xn)
{
    __shared__ float sm[32];
    __shared__ float s_inv;
    const int row = blockIdx.x;
    const float* xr = x + (size_t)row * DIM;
    float ss = 0.f;
    for (int i = threadIdx.x; i < DIM; i += blockDim.x) {
        const float v = xr[i];
        ss = fmaf(v, v, ss);
    }
    ss = block_sum(ss, sm);
    if (threadIdx.x == 0) s_inv = rsqrtf(ss / (float)DIM + RMS_EPS);
    __syncthreads();
    const float inv = s_inv;
    float* xo = xn + (size_t)row * DIM;
    for (int i = threadIdx.x; i < DIM; i += blockDim.x)
        xo[i] = tf32_rna(xr[i] * inv * w[i]);
}

// ------- per-token stats: |q_t|^2, |k_t|^2, q_{t-1}.k_t -------------------
__global__ void qkstats_kernel(const float* __restrict__ q,
                               const float* __restrict__ k,
                               float* __restrict__ nq2,
                               float* __restrict__ nk2,
                               float* __restrict__ dqk)
{
    __shared__ float sm[32];
    const int t = blockIdx.x;
    const float* qr = q + (size_t)t * DIM;
    const float* kr = k + (size_t)t * DIM;
    float sq = 0.f, sk = 0.f, sd = 0.f;
    for (int i = threadIdx.x; i < DIM; i += blockDim.x) {
        const float qv = qr[i], kv = kr[i];
        sq = fmaf(qv, qv, sq);
        sk = fmaf(kv, kv, sk);
        if (t > 0) sd = fmaf(qr[i - DIM], kv, sd);
    }
    sq = block_sum(sq, sm);
    __syncthreads();
    sk = block_sum(sk, sm);
    __syncthreads();
    sd = block_sum(sd, sm);
    if (threadIdx.x == 0) {
        nq2[t] = sq;
        nk2[t] = sk;
        dqk[t] = (t > 0) ? sd : 0.f;
    }
}

// ------- boundary probs -> scan coefficients a_t, c_t ---------------------
__global__ void pcoef_kernel(const float* __restrict__ nq2,
                             const float* __restrict__ nk2,
                             const float* __restrict__ dqk,
                             const int* __restrict__ cu, int nseq,
                             float* __restrict__ a, float* __restrict__ c)
{
    const int t = blockIdx.x * blockDim.x + threadIdx.x;
    if (t >= T_TOK) return;
    bool ss = false;
    for (int i = 0; i < nseq; ++i) ss |= (cu[i] == t);
    float p;
    if (t == 0 || ss) {
        p = 1.0f;
    } else {
        const float cosv = dqk[t] * rsqrtf(nq2[t - 1] * nk2[t]);
        p = (1.0f - cosv) * 0.5f;
    }
    p = fminf(fmaxf(p, EPS_P), 1.0f - EPS_P);
    const bool b = (p >= 0.5f);
    a[t] = (ss || t == 0) ? 0.f : (b ? 1.f - p : 1.f);
    c[t] = b ? p : 0.f;
}

// ------- segmented EMA scan: h_t = a_t h_{t-1} + c_t z_t ------------------
__global__ void ema_scan_kernel(const float* __restrict__ z,
                                const float* __restrict__ a,
                                const float* __restrict__ c,
                                const int* __restrict__ cu,
                                float* __restrict__ out)
{
    __shared__ float sa[1024];
    __shared__ float sc[1024];
    const int seg = blockIdx.y;
    const int t0 = cu[seg], t1 = cu[seg + 1];
    const int ch = blockIdx.x * blockDim.x + threadIdx.x;
    float h = 0.f;
    for (int base = t0; base < t1; base += 1024) {
        const int len = min(1024, t1 - base);
        __syncthreads();
        for (int i = threadIdx.x; i < len; i += blockDim.x) {
            sa[i] = a[base + i];
            sc[i] = c[base + i];
        }
        __syncthreads();
        for (int i = 0; i < len; ++i) {
            const size_t off = (size_t)(base + i) * DIM + ch;
            const float zv = z[off];
            h = fmaf(sa[i], h, sc[i] * zv);
            out[off] = h;
        }
    }
}

// ---------------- launch ----------------
extern "C" void kernel_launch(void* const* d_in, const int* in_sizes, int n_in,
                              void* d_out, int out_size)
{
    const float* x      = (const float*)d_in[0];
    const float* Wq     = (const float*)d_in[1];
    const float* Wk     = (const float*)d_in[2];
    const float* fc1    = (const float*)d_in[3];
    const float* fc2    = (const float*)d_in[4];
    const float* norm_w = (const float*)d_in[5];
    const int*   cu     = (const int*)d_in[6];
    float*       out    = (float*)d_out;
    const int nseq = in_sizes[6] - 1;

    float *xhi, *xlo, *wqth, *wqtl, *wkth, *wktl, *fc1t, *fc2t;
    float *q, *k, *xn, *s, *z, *nq, *nk, *dqk, *a, *c;
    cudaGetSymbolAddress((void**)&xhi,  g_xhi);
    cudaGetSymbolAddress((void**)&xlo,  g_xlo);
    cudaGetSymbolAddress((void**)&wqth, g_wqth);
    cudaGetSymbolAddress((void**)&wqtl, g_wqtl);
    cudaGetSymbolAddress((void**)&wkth, g_wkth);
    cudaGetSymbolAddress((void**)&wktl, g_wktl);
    cudaGetSymbolAddress((void**)&fc1t, g_fc1t);
    cudaGetSymbolAddress((void**)&fc2t, g_fc2t);
    cudaGetSymbolAddress((void**)&q,    g_q);
    cudaGetSymbolAddress((void**)&k,    g_k);
    cudaGetSymbolAddress((void**)&xn,   g_xn);
    cudaGetSymbolAddress((void**)&s,    g_s);
    cudaGetSymbolAddress((void**)&z,    g_z);
    cudaGetSymbolAddress((void**)&nq,   g_nq);
    cudaGetSymbolAddress((void**)&nk,   g_nk);
    cudaGetSymbolAddress((void**)&dqk,  g_dqk);
    cudaGetSymbolAddress((void**)&a,    g_a);
    cudaGetSymbolAddress((void**)&c,    g_c);

    const int SMEM_SPLIT = 2 * 4 * TILEF * 4;   // 147456 B (split q/k kernel)
    const int SMEM_G2    = 3 * STGF2 * 4;       // 165888 B (256-row kernel)
    cudaFuncSetAttribute(gemm_mma<true, 2>,
                         cudaFuncAttributeMaxDynamicSharedMemorySize, SMEM_SPLIT);
    cudaFuncSetAttribute(gemm2<true, 3>,
                         cudaFuncAttributeMaxDynamicSharedMemorySize, SMEM_G2);
    cudaFuncSetAttribute(gemm2<false, 3>,
                         cudaFuncAttributeMaxDynamicSharedMemorySize, SMEM_G2);

    // ---- pre-passes: splits + transposed tf32 weights ----
    {
        const size_t n = (size_t)T_TOK * DIM;
        split_kernel<<<(unsigned)((n + 255) / 256), 256>>>(x, xhi, xlo);
    }
    transpose_split<<<dim3(DIM / 32, DIM / 32), dim3(32, 8)>>>(Wq, wqth, wqtl, DIM, DIM);
    transpose_split<<<dim3(DIM / 32, DIM / 32), dim3(32, 8)>>>(Wk, wkth, wktl, DIM, DIM);
    transpose_rna<<<dim3(2 * HID / 32, DIM / 32), dim3(32, 8)>>>(fc1, fc1t, DIM, 2 * HID);
    transpose_rna<<<dim3(DIM / 32, HID / 32), dim3(32, 8)>>>(fc2, fc2t, HID, DIM);

    // ---- q, k via 3xTF32 split GEMM (sign-critical path), band-swizzled ----
    gemm_mma<true, 2><<<(T_TOK / 128) * (DIM / 128), 256, SMEM_SPLIT>>>(
        xhi, xlo, wqth, wqtl, nullptr, q, DIM, DIM, T_TOK / 128);
    gemm_mma<true, 2><<<(T_TOK / 128) * (DIM / 128), 256, SMEM_SPLIT>>>(
        xhi, xlo, wkth, wktl, nullptr, k, DIM, DIM, T_TOK / 128);

    // boundary statistics and scan coefficients
    qkstats_kernel<<<T_TOK, 256>>>(q, k, nq, nk, dqk);
    pcoef_kernel<<<T_TOK / 256, 256>>>(nq, nk, dqk, cu, nseq, a, c);

    // xn = rmsnorm(x)  (tf32-rounded)
    rmsnorm_kernel<<<T_TOK, 256>>>(x, norm_w, xn);

    // s = silu(xn@fc1_g) * (xn@fc1_h)   -- fused fc1 + SwiGLU, band-swizzled
    gemm2<true, 3><<<(T_TOK / 256) * (HID / 64), 256, SMEM_G2>>>(
        xn, fc1t, nullptr, s, HID, DIM, T_TOK / 256);

    // z = x + s @ fc2, band-swizzled
    gemm2<false, 3><<<(T_TOK / 256) * (DIM / 128), 256, SMEM_G2>>>(
        s, fc2t, x, z, DIM, HID, T_TOK / 256);

    // segmented EMA scan -> out
    ema_scan_kernel<<<dim3(DIM / 256, nseq), 256>>>(z, a, c, cu, out);
}

// round 14
// speedup vs baseline: 1.5277x; 1.0112x over previous
#include <cuda_runtime.h>
#include <cuda_bf16.h>
#include <math.h>
#include <stdint.h>

// ---------------- problem constants (fixed-shape problem) ----------------
#define T_TOK 8192
#define DIM   2048
#define HID   8192
#define EPS_P 1e-4f
#define RMS_EPS 1e-5f

// smem tile geometry: rows x 32 tf32, row stride 36 floats (conflict-free)
#define SK    36
#define GN    16      // band width (n-tiles) for the L2 swizzle

// ---------------- scratch (static device globals; no allocs) -------------
__device__ float g_xhi [(size_t)T_TOK * DIM];
__device__ float g_xlo [(size_t)T_TOK * DIM];
__device__ float g_wqth[(size_t)DIM * DIM];
__device__ float g_wqtl[(size_t)DIM * DIM];
__device__ float g_wkth[(size_t)DIM * DIM];
__device__ float g_wktl[(size_t)DIM * DIM];
__device__ float g_fc1t[(size_t)2 * HID * DIM];
__device__ float g_fc2t[(size_t)DIM * HID];
__device__ float g_q  [(size_t)T_TOK * DIM];
__device__ float g_k  [(size_t)T_TOK * DIM];
__device__ float g_xn [(size_t)T_TOK * DIM];
__device__ float g_s  [(size_t)T_TOK * HID];
__device__ float g_z  [(size_t)T_TOK * DIM];
__device__ float g_nq [T_TOK];
__device__ float g_nk [T_TOK];
__device__ float g_dqk[T_TOK];
__device__ float g_a  [T_TOK];
__device__ float g_c  [T_TOK];

// ---------------- PTX helpers ----------------
__device__ __forceinline__ uint32_t smem_u32(const void* p) {
    uint32_t a;
    asm("{ .reg .u64 t; cvta.to.shared.u64 t, %1; cvt.u32.u64 %0, t; }" : "=r"(a) : "l"(p));
    return a;
}
__device__ __forceinline__ float tf32_rna(float v) {
    uint32_t r;
    asm("cvt.rna.tf32.f32 %0, %1;" : "=r"(r) : "f"(v));
    return __uint_as_float(r);
}
__device__ __forceinline__ void cp16(uint32_t dst, const float* src) {
    asm volatile("cp.async.cg.shared.global [%0], [%1], 16;" :: "r"(dst), "l"(src) : "memory");
}
__device__ __forceinline__ void cp_commit() {
    asm volatile("cp.async.commit_group;" ::: "memory");
}
template<int N> __device__ __forceinline__ void cp_wait() {
    asm volatile("cp.async.wait_group %0;" :: "n"(N) : "memory");
}

// m16n8k8 row.col tf32 MMA: D += A*B, fp32 accumulate
#define MMA8(c, a, b0, b1)                                                      \
    asm volatile(                                                               \
        "mma.sync.aligned.m16n8k8.row.col.f32.tf32.tf32.f32 "                   \
        "{%0,%1,%2,%3}, {%4,%5,%6,%7}, {%8,%9}, {%0,%1,%2,%3};"                 \
        : "+f"((c)[0]), "+f"((c)[1]), "+f"((c)[2]), "+f"((c)[3])                \
        : "r"((a)[0]), "r"((a)[1]), "r"((a)[2]), "r"((a)[3]),                   \
          "r"(b0), "r"(b1))

// band swizzle: 1D grid -> (m_tile, n_tile); m fastest inside a GN-wide band
__device__ __forceinline__ void swz_tile(int bid, int tiles_m, int& mt, int& nt) {
    const int per_band = GN * tiles_m;
    const int band = bid / per_band;
    const int loc  = bid % per_band;
    mt = loc / GN;
    nt = band * GN + loc % GN;
}

// ============ unified 128-row GEMM, 2 CTAs/SM =============================
// BM=128, 2 smem stages, 256 threads, 8 warps as 4(M) x 2(N).
// SPLIT (q/k): 3xTF32 hi/lo; A2/Bt2 are lo parts; BN columns per CTA.
// GLU (fc1):   BN=64 output cols; B region holds hh rows [n0,n0+64) and
//              g rows [HID+n0,+64); writes s = tf32(silu(g)*hh).
// plain (fc2): C = A@Bt^T + res.
template<int BN, bool SPLIT, bool GLU>
__global__ __launch_bounds__(256, 2)
void gemm128(const float* __restrict__ A,  const float* __restrict__ A2,
             const float* __restrict__ Bt, const float* __restrict__ Bt2,
             const float* __restrict__ res, float* __restrict__ C,
             int N, int K, int tiles_m)
{
    constexpr int AR = SPLIT ? 256 : 128;                 // A smem rows
    constexpr int BR = SPLIT ? 2 * BN : (GLU ? 128 : BN); // B smem rows
    constexpr int SR = AR + BR;                           // rows per stage
    constexpr int STGF = SR * SK;                         // floats per stage
    constexpr int NH = GLU ? 2 : 1;
    constexpr int NT = GLU ? 4 : (BN / 16);               // 8-col tiles per warp
    constexpr int LITER = SR / 32;                        // cp16 iters (256 thr)

    extern __shared__ float sm[];
    const uint32_t sbase = smem_u32(sm);

    const int tid  = threadIdx.x;
    const int lane = tid & 31, wid = tid >> 5;
    const int warpM = wid & 3, warpN = wid >> 2;

    int mti, nti;
    swz_tile(blockIdx.x, tiles_m, mti, nti);
    const int m0 = mti * 128;
    const int n0 = nti * BN;
    const int KT = K >> 5;

    auto load_stage = [&](int s, int kt) {
        const uint32_t st = sbase + (uint32_t)s * (STGF * 4);
        #pragma unroll
        for (int it = 0; it < LITER; ++it) {
            const int idx = tid + it * 256;
            const int r = idx >> 3, g = idx & 7;
            const uint32_t d = st + (uint32_t)(r * SK + g * 4) * 4;
            const float* src;
            if (r < 128) {
                src = A + (size_t)(m0 + r) * K;
            } else if (SPLIT && r < 256) {
                src = A2 + (size_t)(m0 + r - 128) * K;
            } else {
                const int rb = r - AR;
                if (SPLIT) {
                    src = (rb < BN) ? Bt  + (size_t)(n0 + rb) * K
                                    : Bt2 + (size_t)(n0 + rb - BN) * K;
                } else if (GLU) {
                    const int brow = (rb < 64) ? (n0 + rb) : (HID + n0 + rb - 64);
                    src = Bt + (size_t)brow * K;
                } else {
                    src = Bt + (size_t)(n0 + rb) * K;
                }
            }
            cp16(d, src + kt * 32 + g * 4);
        }
    };

    float acc[NH][2][NT][4];
    #pragma unroll
    for (int h = 0; h < NH; ++h)
        #pragma unroll
        for (int mt = 0; mt < 2; ++mt)
            #pragma unroll
            for (int nt = 0; nt < NT; ++nt)
                #pragma unroll
                for (int j = 0; j < 4; ++j) acc[h][mt][nt][j] = 0.f;

    load_stage(0, 0); cp_commit();

    for (int kt = 0; kt < KT; ++kt) {
        __syncthreads();
        if (kt + 1 < KT) load_stage((kt + 1) & 1, kt + 1);
        cp_commit();
        cp_wait<1>();
        __syncthreads();

        const float* sA  = sm + (kt & 1) * STGF;
        const float* sAl = sA + 128 * SK;        // valid iff SPLIT
        const float* sB  = sA + AR * SK;

        #pragma unroll
        for (int ks = 0; ks < 4; ++ks) {
            const int k0 = ks * 8 + (lane & 3);
            uint32_t aH[2][4], aL[2][4];
            #pragma unroll
            for (int mt = 0; mt < 2; ++mt) {
                const int r = warpM * 32 + mt * 16 + (lane >> 2);
                aH[mt][0] = __float_as_uint(sA[r * SK + k0]);
                aH[mt][1] = __float_as_uint(sA[(r + 8) * SK + k0]);
                aH[mt][2] = __float_as_uint(sA[r * SK + k0 + 4]);
                aH[mt][3] = __float_as_uint(sA[(r + 8) * SK + k0 + 4]);
                if (SPLIT) {
                    aL[mt][0] = __float_as_uint(sAl[r * SK + k0]);
                    aL[mt][1] = __float_as_uint(sAl[(r + 8) * SK + k0]);
                    aL[mt][2] = __float_as_uint(sAl[r * SK + k0 + 4]);
                    aL[mt][3] = __float_as_uint(sAl[(r + 8) * SK + k0 + 4]);
                }
            }
            #pragma unroll
            for (int h = 0; h < NH; ++h) {
                #pragma unroll
                for (int nt = 0; nt < NT; ++nt) {
                    const int n = (GLU ? (h * 64 + warpN * 32) : (warpN * (BN / 2)))
                                + nt * 8 + (lane >> 2);
                    const uint32_t bH0 = __float_as_uint(sB[n * SK + k0]);
                    const uint32_t bH1 = __float_as_uint(sB[n * SK + k0 + 4]);
                    #pragma unroll
                    for (int mt = 0; mt < 2; ++mt)
                        MMA8(acc[h][mt][nt], aH[mt], bH0, bH1);
                    if (SPLIT) {
                        const uint32_t bL0 = __float_as_uint(sB[(BN + n) * SK + k0]);
                        const uint32_t bL1 = __float_as_uint(sB[(BN + n) * SK + k0 + 4]);
                        #pragma unroll
                        for (int mt = 0; mt < 2; ++mt) {
                            MMA8(acc[h][mt][nt], aL[mt], bH0, bH1);   // lo*hi
                            MMA8(acc[h][mt][nt], aH[mt], bL0, bL1);   // hi*lo
                        }
                    }
                }
            }
        }
    }

    // epilogue
    #pragma unroll
    for (int mt = 0; mt < 2; ++mt) {
        const int r = m0 + warpM * 32 + mt * 16 + (lane >> 2);
        #pragma unroll
        for (int nt = 0; nt < NT; ++nt) {
            const int c = n0 + (GLU ? warpN * 32 : warpN * (BN / 2))
                        + nt * 8 + ((lane & 3) << 1);
            if (GLU) {
                #pragma unroll
                for (int j = 0; j < 2; ++j) {      // j=0: row r, j=1: row r+8
                    const size_t o = (size_t)(r + j * 8) * N + c;
                    const float hh0 = acc[0][mt][nt][2 * j];
                    const float hh1 = acc[0][mt][nt][2 * j + 1];
                    const float gg0 = acc[1][mt][nt][2 * j];
                    const float gg1 = acc[1][mt][nt][2 * j + 1];
                    float2 v;
                    v.x = tf32_rna(hh0 * (gg0 / (1.f + expf(-gg0))));
                    v.y = tf32_rna(hh1 * (gg1 / (1.f + expf(-gg1))));
                    *(float2*)(C + o) = v;
                }
            } else {
                float2 v0 = make_float2(acc[0][mt][nt][0], acc[0][mt][nt][1]);
                float2 v1 = make_float2(acc[0][mt][nt][2], acc[0][mt][nt][3]);
                const size_t o0 = (size_t)r * N + c;
                const size_t o1 = (size_t)(r + 8) * N + c;
                if (res) {
                    const float2 d0 = *(const float2*)(res + o0);
                    const float2 d1 = *(const float2*)(res + o1);
                    v0.x += d0.x; v0.y += d0.y;
                    v1.x += d1.x; v1.y += d1.y;
                }
                *(float2*)(C + o0) = v0;
                *(float2*)(C + o1) = v1;
            }
        }
    }
}

// ---------------- pre-passes ----------------
__global__ void split_kernel(const float* __restrict__ x,
                             float* __restrict__ hi, float* __restrict__ lo)
{
    const size_t i = (size_t)blockIdx.x * blockDim.x + threadIdx.x;
    if (i >= (size_t)T_TOK * DIM) return;
    const float v = x[i];
    const float h = tf32_rna(v);
    hi[i] = h;
    lo[i] = tf32_rna(v - h);
}

__global__ void transpose_rna(const float* __restrict__ W, float* __restrict__ Wt,
                              int K, int N)
{
    __shared__ float t[32][33];
    const int n0 = blockIdx.x * 32, k0 = blockIdx.y * 32;
    for (int i = threadIdx.y; i < 32; i += 8)
        t[i][threadIdx.x] = W[(size_t)(k0 + i) * N + n0 + threadIdx.x];
    __syncthreads();
    for (int i = threadIdx.y; i < 32; i += 8)
        Wt[(size_t)(n0 + i) * K + k0 + threadIdx.x] = tf32_rna(t[threadIdx.x][i]);
}

__global__ void transpose_split(const float* __restrict__ W,
                                float* __restrict__ WtH, float* __restrict__ WtL,
                                int K, int N)
{
    __shared__ float t[32][33];
    const int n0 = blockIdx.x * 32, k0 = blockIdx.y * 32;
    for (int i = threadIdx.y; i < 32; i += 8)
        t[i][threadIdx.x] = W[(size_t)(k0 + i) * N + n0 + threadIdx.x];
    __syncthreads();
    for (int i = threadIdx.y; i < 32; i += 8) {
        const float v = t[threadIdx.x][i];
        const float h = tf32_rna(v);
        const size_t o = (size_t)(n0 + i) * K + k0 + threadIdx.x;
        WtH[o] = h;
        WtL[o] = tf32_rna(v - h);
    }
}

// ---------------- block reduction helper ----------------
__device__ __forceinline__ float block_sum(float v, float* sm)
{
    #pragma unroll
    for (int o = 16; o > 0; o >>= 1) v += __shfl_down_sync(0xffffffffu, v, o);
    const int lane = threadIdx.x & 31, wid = threadIdx.x >> 5;
    if (lane == 0) sm[wid] = v;
    __syncthreads();
    v = (threadIdx.x < (blockDim.x >> 5)) ? sm[threadIdx.x] : 0.f;
    if (wid == 0) {
        #pragma unroll
        for (int o = 16; o > 0; o >>= 1) v += __shfl_down_sync(0xffffffffu, v, o);
    }
    return v;
}

// ---------------- rmsnorm (emits rna-tf32 values) ----------------
__global__ void rmsnorm_kernel(const float* __restrict__ x,
                               const float* __restrict__ w,
                               float* __restrict__ xn)
{
    __shared__ float sm[32];
    __shared__ float s_inv;
    const int row = blockIdx.x;
    const float* xr = x + (size_t)row * DIM;
    float ss = 0.f;
    for (int i = threadIdx.x; i < DIM; i += blockDim.x) {
        const float v = xr[i];
        ss = fmaf(v, v, ss);
    }
    ss = block_sum(ss, sm);
    if (threadIdx.x == 0) s_inv = rsqrtf(ss / (float)DIM + RMS_EPS);
    __syncthreads();
    const float inv = s_inv;
    float* xo = xn + (size_t)row * DIM;
    for (int i = threadIdx.x; i < DIM; i += blockDim.x)
        xo[i] = tf32_rna(xr[i] * inv * w[i]);
}

// ------- per-token stats: |q_t|^2, |k_t|^2, q_{t-1}.k_t -------------------
__global__ void qkstats_kernel(const float* __restrict__ q,
                               const float* __restrict__ k,
                               float* __restrict__ nq2,
                               float* __restrict__ nk2,
                               float* __restrict__ dqk)
{
    __shared__ float sm[32];
    const int t = blockIdx.x;
    const float* qr = q + (size_t)t * DIM;
    const float* kr = k + (size_t)t * DIM;
    float sq = 0.f, sk = 0.f, sd = 0.f;
    for (int i = threadIdx.x; i < DIM; i += blockDim.x) {
        const float qv = qr[i], kv = kr[i];
        sq = fmaf(qv, qv, sq);
        sk = fmaf(kv, kv, sk);
        if (t > 0) sd = fmaf(qr[i - DIM], kv, sd);
    }
    sq = block_sum(sq, sm);
    __syncthreads();
    sk = block_sum(sk, sm);
    __syncthreads();
    sd = block_sum(sd, sm);
    if (threadIdx.x == 0) {
        nq2[t] = sq;
        nk2[t] = sk;
        dqk[t] = (t > 0) ? sd : 0.f;
    }
}

// ------- boundary probs -> scan coefficients a_t, c_t ---------------------
__global__ void pcoef_kernel(const float* __restrict__ nq2,
                             const float* __restrict__ nk2,
                             const float* __restrict__ dqk,
                             const int* __restrict__ cu, int nseq,
                             float* __restrict__ a, float* __restrict__ c)
{
    const int t = blockIdx.x * blockDim.x + threadIdx.x;
    if (t >= T_TOK) return;
    bool ss = false;
    for (int i = 0; i < nseq; ++i) ss |= (cu[i] == t);
    float p;
    if (t == 0 || ss) {
        p = 1.0f;
    } else {
        const float cosv = dqk[t] * rsqrtf(nq2[t - 1] * nk2[t]);
        p = (1.0f - cosv) * 0.5f;
    }
    p = fminf(fmaxf(p, EPS_P), 1.0f - EPS_P);
    const bool b = (p >= 0.5f);
    a[t] = (ss || t == 0) ? 0.f : (b ? 1.f - p : 1.f);
    c[t] = b ? p : 0.f;
}

// ------- segmented EMA scan: h_t = a_t h_{t-1} + c_t z_t ------------------
__global__ void ema_scan_kernel(const float* __restrict__ z,
                                const float* __restrict__ a,
                                const float* __restrict__ c,
                                const int* __restrict__ cu,
                                float* __restrict__ out)
{
    __shared__ float sa[1024];
    __shared__ float sc[1024];
    const int seg = blockIdx.y;
    const int t0 = cu[seg], t1 = cu[seg + 1];
    const int ch = blockIdx.x * blockDim.x + threadIdx.x;
    float h = 0.f;
    for (int base = t0; base < t1; base += 1024) {
        const int len = min(1024, t1 - base);
        __syncthreads();
        for (int i = threadIdx.x; i < len; i += blockDim.x) {
            sa[i] = a[base + i];
            sc[i] = c[base + i];
        }
        __syncthreads();
        for (int i = 0; i < len; ++i) {
            const size_t off = (size_t)(base + i) * DIM + ch;
            const float zv = z[off];
            h = fmaf(sa[i], h, sc[i] * zv);
            out[off] = h;
        }
    }
}

// ---------------- launch ----------------
extern "C" void kernel_launch(void* const* d_in, const int* in_sizes, int n_in,
                              void* d_out, int out_size)
{
    const float* x      = (const float*)d_in[0];
    const float* Wq     = (const float*)d_in[1];
    const float* Wk     = (const float*)d_in[2];
    const float* fc1    = (const float*)d_in[3];
    const float* fc2    = (const float*)d_in[4];
    const float* norm_w = (const float*)d_in[5];
    const int*   cu     = (const int*)d_in[6];
    float*       out    = (float*)d_out;
    const int nseq = in_sizes[6] - 1;

    float *xhi, *xlo, *wqth, *wqtl, *wkth, *wktl, *fc1t, *fc2t;
    float *q, *k, *xn, *s, *z, *nq, *nk, *dqk, *a, *c;
    cudaGetSymbolAddress((void**)&xhi,  g_xhi);
    cudaGetSymbolAddress((void**)&xlo,  g_xlo);
    cudaGetSymbolAddress((void**)&wqth, g_wqth);
    cudaGetSymbolAddress((void**)&wqtl, g_wqtl);
    cudaGetSymbolAddress((void**)&wkth, g_wkth);
    cudaGetSymbolAddress((void**)&wktl, g_wktl);
    cudaGetSymbolAddress((void**)&fc1t, g_fc1t);
    cudaGetSymbolAddress((void**)&fc2t, g_fc2t);
    cudaGetSymbolAddress((void**)&q,    g_q);
    cudaGetSymbolAddress((void**)&k,    g_k);
    cudaGetSymbolAddress((void**)&xn,   g_xn);
    cudaGetSymbolAddress((void**)&s,    g_s);
    cudaGetSymbolAddress((void**)&z,    g_z);
    cudaGetSymbolAddress((void**)&nq,   g_nq);
    cudaGetSymbolAddress((void**)&nk,   g_nk);
    cudaGetSymbolAddress((void**)&dqk,  g_dqk);
    cudaGetSymbolAddress((void**)&a,    g_a);
    cudaGetSymbolAddress((void**)&c,    g_c);

    // stage sizes: split q/k 384 rows, others 256 rows; 2 stages each
    const int SMEM_QK = 2 * 384 * SK * 4;   // 110592 B -> 2 CTAs/SM (221 KB)
    const int SMEM_G  = 2 * 256 * SK * 4;   //  73728 B -> 2 CTAs/SM (147 KB)
    cudaFuncSetAttribute((const void*)gemm128<64, true, false>,
                         cudaFuncAttributeMaxDynamicSharedMemorySize, SMEM_QK);
    cudaFuncSetAttribute((const void*)gemm128<64, false, true>,
                         cudaFuncAttributeMaxDynamicSharedMemorySize, SMEM_G);
    cudaFuncSetAttribute((const void*)gemm128<128, false, false>,
                         cudaFuncAttributeMaxDynamicSharedMemorySize, SMEM_G);

    // ---- pre-passes: splits + transposed tf32 weights ----
    {
        const size_t n = (size_t)T_TOK * DIM;
        split_kernel<<<(unsigned)((n + 255) / 256), 256>>>(x, xhi, xlo);
    }
    transpose_split<<<dim3(DIM / 32, DIM / 32), dim3(32, 8)>>>(Wq, wqth, wqtl, DIM, DIM);
    transpose_split<<<dim3(DIM / 32, DIM / 32), dim3(32, 8)>>>(Wk, wkth, wktl, DIM, DIM);
    transpose_rna<<<dim3(2 * HID / 32, DIM / 32), dim3(32, 8)>>>(fc1, fc1t, DIM, 2 * HID);
    transpose_rna<<<dim3(DIM / 32, HID / 32), dim3(32, 8)>>>(fc2, fc2t, HID, DIM);

    // ---- q, k via 3xTF32 split GEMM (sign-critical path) ----
    gemm128<64, true, false><<<(T_TOK / 128) * (DIM / 64), 256, SMEM_QK>>>(
        xhi, xlo, wqth, wqtl, nullptr, q, DIM, DIM, T_TOK / 128);
    gemm128<64, true, false><<<(T_TOK / 128) * (DIM / 64), 256, SMEM_QK>>>(
        xhi, xlo, wkth, wktl, nullptr, k, DIM, DIM, T_TOK / 128);

    // boundary statistics and scan coefficients
    qkstats_kernel<<<T_TOK, 256>>>(q, k, nq, nk, dqk);
    pcoef_kernel<<<T_TOK / 256, 256>>>(nq, nk, dqk, cu, nseq, a, c);

    // xn = rmsnorm(x)  (tf32-rounded)
    rmsnorm_kernel<<<T_TOK, 256>>>(x, norm_w, xn);

    // s = silu(xn@fc1_g) * (xn@fc1_h)   -- fused fc1 + SwiGLU
    gemm128<64, false, true><<<(T_TOK / 128) * (HID / 64), 256, SMEM_G>>>(
        xn, nullptr, fc1t, nullptr, nullptr, s, HID, DIM, T_TOK / 128);

    // z = x + s @ fc2
    gemm128<128, false, false><<<(T_TOK / 128) * (DIM / 128), 256, SMEM_G>>>(
        s, nullptr, fc2t, nullptr, x, z, DIM, HID, T_TOK / 128);

    // segmented EMA scan -> out
    ema_scan_kernel<<<dim3(DIM / 256, nseq), 256>>>(z, a, c, cu, out);
}

// round 16
// speedup vs baseline: 2.5440x; 1.6653x over previous
#include <cuda_runtime.h>
#include <cuda_fp16.h>
#include <math.h>
#include <stdint.h>

// ---------------- problem constants (fixed-shape problem) ----------------
#define T_TOK 8192
#define DIM   2048
#define HID   8192
#define EPS_P 1e-4f
#define RMS_EPS 1e-5f

// fp16 smem tile: rows x 32 halves, row stride 40 halves (80B, conflict-free:
// bank = (20*r + c) mod 32 hits all 32 banks for r in 8-row group, c in 0..3)
#define SKH   40
#define GN    16      // band width (n-tiles) for the L2 swizzle
#define LOSC  4096.0f          // lo-part pre-scale (2^12)
#define LOSCI 2.44140625e-4f   // 2^-12

// ---------------- scratch (static device globals; no allocs) -------------
__device__ __half g_xhi [(size_t)T_TOK * DIM];
__device__ __half g_xlo [(size_t)T_TOK * DIM];          // scaled by 2^12
__device__ __half g_wqth[(size_t)DIM * DIM];
__device__ __half g_wqtl[(size_t)DIM * DIM];            // scaled by 2^12
__device__ __half g_wkth[(size_t)DIM * DIM];
__device__ __half g_wktl[(size_t)DIM * DIM];            // scaled by 2^12
__device__ __half g_fc1t[(size_t)2 * HID * DIM];
__device__ __half g_fc2t[(size_t)DIM * HID];
__device__ __half g_xn [(size_t)T_TOK * DIM];
__device__ __half g_s  [(size_t)T_TOK * HID];
__device__ float  g_q  [(size_t)T_TOK * DIM];
__device__ float  g_k  [(size_t)T_TOK * DIM];
__device__ float  g_z  [(size_t)T_TOK * DIM];
__device__ float  g_nq [T_TOK];
__device__ float  g_nk [T_TOK];
__device__ float  g_dqk[T_TOK];
__device__ float  g_a  [T_TOK];
__device__ float  g_c  [T_TOK];

// ---------------- PTX helpers ----------------
__device__ __forceinline__ uint32_t smem_u32(const void* p) {
    uint32_t a;
    asm("{ .reg .u64 t; cvta.to.shared.u64 t, %1; cvt.u32.u64 %0, t; }" : "=r"(a) : "l"(p));
    return a;
}
__device__ __forceinline__ void cp16(uint32_t dst, const void* src) {
    asm volatile("cp.async.cg.shared.global [%0], [%1], 16;" :: "r"(dst), "l"(src) : "memory");
}
__device__ __forceinline__ void cp_commit() {
    asm volatile("cp.async.commit_group;" ::: "memory");
}
template<int N> __device__ __forceinline__ void cp_wait() {
    asm volatile("cp.async.wait_group %0;" :: "n"(N) : "memory");
}

// m16n8k16 row.col fp16 MMA, fp32 accumulate: D += A*B
#define MMAH(c, a, b0, b1)                                                      \
    asm volatile(                                                               \
        "mma.sync.aligned.m16n8k16.row.col.f32.f16.f16.f32 "                    \
        "{%0,%1,%2,%3}, {%4,%5,%6,%7}, {%8,%9}, {%0,%1,%2,%3};"                 \
        : "+f"((c)[0]), "+f"((c)[1]), "+f"((c)[2]), "+f"((c)[3])                \
        : "r"((a)[0]), "r"((a)[1]), "r"((a)[2]), "r"((a)[3]),                   \
          "r"(b0), "r"(b1))

// band swizzle: 1D grid -> (m_tile, n_tile); m fastest inside a GN-wide band
__device__ __forceinline__ void swz_tile(int bid, int tiles_m, int& mt, int& nt) {
    const int per_band = GN * tiles_m;
    const int band = bid / per_band;
    const int loc  = bid % per_band;
    mt = loc / GN;
    nt = band * GN + loc % GN;
}

// load A fragment (4 regs) for m16n8k16 from fp16 smem row-major (SKH stride)
__device__ __forceinline__ void frag_a(uint32_t* a, const __half* base,
                                       int r, int koff /*halves*/, int c) {
    const __half* p = base + r * SKH + koff + 2 * c;
    a[0] = *(const uint32_t*)(p);
    a[1] = *(const uint32_t*)(p + 8 * SKH);
    a[2] = *(const uint32_t*)(p + 8);
    a[3] = *(const uint32_t*)(p + 8 * SKH + 8);
}

// ============ unified fp16 GEMM, BM=128, 2 stages, 2 CTAs/SM ==============
// 256 threads, 8 warps as 4(M) x 2(N). Operands fp16 [rows][K] row-major.
// SPLIT (q/k): A2/Bt2 are 2^12-scaled lo parts; out = accH + 2^-12*accL.
// GLU (fc1):   BN=64 out cols; B rows [n0,+64)=hh, [HID+n0,+64)=g;
//              writes Ch = fp16(silu(g)*hh).
// plain (fc2): Cf = A@Bt^T + res (fp32).
template<int BN, bool SPLIT, bool GLU>
__global__ __launch_bounds__(256, 2)
void gemm16(const __half* __restrict__ A,  const __half* __restrict__ A2,
            const __half* __restrict__ Bt, const __half* __restrict__ Bt2,
            const float* __restrict__ res, float* __restrict__ Cf,
            __half* __restrict__ Ch, int N, int K, int tiles_m)
{
    constexpr int AR = SPLIT ? 256 : 128;
    constexpr int BR = SPLIT ? 2 * BN : (GLU ? 128 : BN);
    constexpr int SR = AR + BR;
    constexpr int STGH = SR * SKH;          // halves per stage
    constexpr int NH = GLU ? 2 : 1;
    constexpr int NT = GLU ? 4 : (BN / 16);
    constexpr int LITER = SR / 64;          // (SR*4 cp16) / 256 threads

    extern __shared__ __half smh[];
    const uint32_t sbase = smem_u32(smh);

    const int tid  = threadIdx.x;
    const int lane = tid & 31, wid = tid >> 5;
    const int warpM = wid & 3, warpN = wid >> 2;
    const int rgrp = lane >> 2, cg = lane & 3;

    int mti, nti;
    swz_tile(blockIdx.x, tiles_m, mti, nti);
    const int m0 = mti * 128;
    const int n0 = nti * BN;
    const int KT = K >> 5;                  // 32 k-halves per chunk

    auto load_stage = [&](int s, int kt) {
        const uint32_t st = sbase + (uint32_t)s * (STGH * 2);
        #pragma unroll
        for (int it = 0; it < LITER; ++it) {
            const int idx = tid + it * 256;
            const int r = idx >> 2, c8 = idx & 3;
            const uint32_t d = st + (uint32_t)(r * SKH + c8 * 8) * 2;
            const __half* src;
            if (r < 128) {
                src = A + (size_t)(m0 + r) * K;
            } else if (SPLIT && r < 256) {
                src = A2 + (size_t)(m0 + r - 128) * K;
            } else {
                const int rb = r - AR;
                if (SPLIT) {
                    src = (rb < BN) ? Bt  + (size_t)(n0 + rb) * K
                                    : Bt2 + (size_t)(n0 + rb - BN) * K;
                } else if (GLU) {
                    const int brow = (rb < 64) ? (n0 + rb) : (HID + n0 + rb - 64);
                    src = Bt + (size_t)brow * K;
                } else {
                    src = Bt + (size_t)(n0 + rb) * K;
                }
            }
            cp16(d, src + kt * 32 + c8 * 8);
        }
    };

    float accH[NH][2][NT][4];
    float accL[SPLIT ? 2 : 1][SPLIT ? NT : 1][4];
    #pragma unroll
    for (int h = 0; h < NH; ++h)
        #pragma unroll
        for (int mt = 0; mt < 2; ++mt)
            #pragma unroll
            for (int nt = 0; nt < NT; ++nt)
                #pragma unroll
                for (int j = 0; j < 4; ++j) accH[h][mt][nt][j] = 0.f;
    if (SPLIT) {
        #pragma unroll
        for (int mt = 0; mt < 2; ++mt)
            #pragma unroll
            for (int nt = 0; nt < NT; ++nt)
                #pragma unroll
                for (int j = 0; j < 4; ++j) accL[mt][nt][j] = 0.f;
    }

    load_stage(0, 0); cp_commit();

    for (int kt = 0; kt < KT; ++kt) {
        __syncthreads();
        if (kt + 1 < KT) load_stage((kt + 1) & 1, kt + 1);
        cp_commit();
        cp_wait<1>();
        __syncthreads();

        const __half* sA  = smh + (kt & 1) * STGH;
        const __half* sAl = sA + 128 * SKH;     // valid iff SPLIT
        const __half* sB  = sA + AR * SKH;

        #pragma unroll
        for (int ks = 0; ks < 2; ++ks) {
            const int koff = ks * 16;
            uint32_t aH[2][4], aL[2][4];
            #pragma unroll
            for (int mt = 0; mt < 2; ++mt) {
                const int r = warpM * 32 + mt * 16 + rgrp;
                frag_a(aH[mt], sA, r, koff, cg);
                if (SPLIT) frag_a(aL[mt], sAl, r, koff, cg);
            }
            #pragma unroll
            for (int h = 0; h < NH; ++h) {
                #pragma unroll
                for (int nt = 0; nt < NT; ++nt) {
                    const int n = (GLU ? (h * 64 + warpN * 32) : (warpN * (BN / 2)))
                                + nt * 8 + rgrp;
                    const __half* bp = sB + n * SKH + koff + 2 * cg;
                    const uint32_t bH0 = *(const uint32_t*)(bp);
                    const uint32_t bH1 = *(const uint32_t*)(bp + 8);
                    #pragma unroll
                    for (int mt = 0; mt < 2; ++mt)
                        MMAH(accH[h][mt][nt], aH[mt], bH0, bH1);
                    if (SPLIT) {
                        const __half* blp = bp + (size_t)BN * SKH;
                        const uint32_t bL0 = *(const uint32_t*)(blp);
                        const uint32_t bL1 = *(const uint32_t*)(blp + 8);
                        #pragma unroll
                        for (int mt = 0; mt < 2; ++mt) {
                            MMAH(accL[mt][nt], aL[mt], bH0, bH1);   // loS*hi
                            MMAH(accL[mt][nt], aH[mt], bL0, bL1);   // hi*loS
                        }
                    }
                }
            }
        }
    }

    // epilogue
    #pragma unroll
    for (int mt = 0; mt < 2; ++mt) {
        const int r = m0 + warpM * 32 + mt * 16 + rgrp;
        #pragma unroll
        for (int nt = 0; nt < NT; ++nt) {
            const int c = n0 + (GLU ? warpN * 32 : warpN * (BN / 2))
                        + nt * 8 + (cg << 1);
            if (GLU) {
                #pragma unroll
                for (int j = 0; j < 2; ++j) {   // j=0: row r, j=1: row r+8
                    const size_t o = (size_t)(r + j * 8) * N + c;
                    const float hh0 = accH[0][mt][nt][2 * j];
                    const float hh1 = accH[0][mt][nt][2 * j + 1];
                    const float gg0 = accH[1][mt][nt][2 * j];
                    const float gg1 = accH[1][mt][nt][2 * j + 1];
                    const float s0 = hh0 * (gg0 / (1.f + expf(-gg0)));
                    const float s1 = hh1 * (gg1 / (1.f + expf(-gg1)));
                    *(__half2*)(Ch + o) = __floats2half2_rn(s0, s1);
                }
            } else {
                float v[4];
                #pragma unroll
                for (int j = 0; j < 4; ++j)
                    v[j] = SPLIT ? accH[0][mt][nt][j] + accL[mt][nt][j] * LOSCI
                                 : accH[0][mt][nt][j];
                const size_t o0 = (size_t)r * N + c;
                const size_t o1 = (size_t)(r + 8) * N + c;
                float2 v0 = make_float2(v[0], v[1]);
                float2 v1 = make_float2(v[2], v[3]);
                if (res) {
                    const float2 d0 = *(const float2*)(res + o0);
                    const float2 d1 = *(const float2*)(res + o1);
                    v0.x += d0.x; v0.y += d0.y;
                    v1.x += d1.x; v1.y += d1.y;
                }
                *(float2*)(Cf + o0) = v0;
                *(float2*)(Cf + o1) = v1;
            }
        }
    }
}

// ---------------- pre-passes ----------------
// x -> fp16 hi + fp16 (lo * 2^12)
__global__ void split16(const float* __restrict__ x,
                        __half* __restrict__ hi, __half* __restrict__ lo)
{
    const size_t i = (size_t)blockIdx.x * blockDim.x + threadIdx.x;
    if (i >= (size_t)T_TOK * DIM) return;
    const float v = x[i];
    const __half h = __float2half_rn(v);
    hi[i] = h;
    lo[i] = __float2half_rn((v - __half2float(h)) * LOSC);
}

// W[K,N] -> Wt[N,K] fp16
__global__ void t16(const float* __restrict__ W, __half* __restrict__ Wt,
                    int K, int N)
{
    __shared__ float t[32][33];
    const int n0 = blockIdx.x * 32, k0 = blockIdx.y * 32;
    for (int i = threadIdx.y; i < 32; i += 8)
        t[i][threadIdx.x] = W[(size_t)(k0 + i) * N + n0 + threadIdx.x];
    __syncthreads();
    for (int i = threadIdx.y; i < 32; i += 8)
        Wt[(size_t)(n0 + i) * K + k0 + threadIdx.x] = __float2half_rn(t[threadIdx.x][i]);
}

// W[K,N] -> WtH[N,K] fp16 hi, WtL[N,K] fp16 (lo * 2^12)
__global__ void tsplit16(const float* __restrict__ W,
                         __half* __restrict__ WtH, __half* __restrict__ WtL,
                         int K, int N)
{
    __shared__ float t[32][33];
    const int n0 = blockIdx.x * 32, k0 = blockIdx.y * 32;
    for (int i = threadIdx.y; i < 32; i += 8)
        t[i][threadIdx.x] = W[(size_t)(k0 + i) * N + n0 + threadIdx.x];
    __syncthreads();
    for (int i = threadIdx.y; i < 32; i += 8) {
        const float v = t[threadIdx.x][i];
        const __half h = __float2half_rn(v);
        const size_t o = (size_t)(n0 + i) * K + k0 + threadIdx.x;
        WtH[o] = h;
        WtL[o] = __float2half_rn((v - __half2float(h)) * LOSC);
    }
}

// ---------------- block reduction helper ----------------
__device__ __forceinline__ float block_sum(float v, float* sm)
{
    #pragma unroll
    for (int o = 16; o > 0; o >>= 1) v += __shfl_down_sync(0xffffffffu, v, o);
    const int lane = threadIdx.x & 31, wid = threadIdx.x >> 5;
    if (lane == 0) sm[wid] = v;
    __syncthreads();
    v = (threadIdx.x < (blockDim.x >> 5)) ? sm[threadIdx.x] : 0.f;
    if (wid == 0) {
        #pragma unroll
        for (int o = 16; o > 0; o >>= 1) v += __shfl_down_sync(0xffffffffu, v, o);
    }
    return v;
}

// ---------------- rmsnorm (emits fp16 values) ----------------
__global__ void rmsnorm_kernel(const float* __restrict__ x,
                               const float* __restrict__ w,
                               __half* __restrict__ xn)
{
    __shared__ float sm[32];
    __shared__ float s_inv;
    const int row = blockIdx.x;
    const float* xr = x + (size_t)row * DIM;
    float ss = 0.f;
    for (int i = threadIdx.x; i < DIM; i += blockDim.x) {
        const float v = xr[i];
        ss = fmaf(v, v, ss);
    }
    ss = block_sum(ss, sm);
    if (threadIdx.x == 0) s_inv = rsqrtf(ss / (float)DIM + RMS_EPS);
    __syncthreads();
    const float inv = s_inv;
    __half* xo = xn + (size_t)row * DIM;
    for (int i = threadIdx.x; i < DIM; i += blockDim.x)
        xo[i] = __float2half_rn(xr[i] * inv * w[i]);
}

// ------- per-token stats: |q_t|^2, |k_t|^2, q_{t-1}.k_t -------------------
__global__ void qkstats_kernel(const float* __restrict__ q,
                               const float* __restrict__ k,
                               float* __restrict__ nq2,
                               float* __restrict__ nk2,
                               float* __restrict__ dqk)
{
    __shared__ float sm[32];
    const int t = blockIdx.x;
    const float* qr = q + (size_t)t * DIM;
    const float* kr = k + (size_t)t * DIM;
    float sq = 0.f, sk = 0.f, sd = 0.f;
    for (int i = threadIdx.x; i < DIM; i += blockDim.x) {
        const float qv = qr[i], kv = kr[i];
        sq = fmaf(qv, qv, sq);
        sk = fmaf(kv, kv, sk);
        if (t > 0) sd = fmaf(qr[i - DIM], kv, sd);
    }
    sq = block_sum(sq, sm);
    __syncthreads();
    sk = block_sum(sk, sm);
    __syncthreads();
    sd = block_sum(sd, sm);
    if (threadIdx.x == 0) {
        nq2[t] = sq;
        nk2[t] = sk;
        dqk[t] = (t > 0) ? sd : 0.f;
    }
}

// ------- boundary probs -> scan coefficients a_t, c_t ---------------------
__global__ void pcoef_kernel(const float* __restrict__ nq2,
                             const float* __restrict__ nk2,
                             const float* __restrict__ dqk,
                             const int* __restrict__ cu, int nseq,
                             float* __restrict__ a, float* __restrict__ c)
{
    const int t = blockIdx.x * blockDim.x + threadIdx.x;
    if (t >= T_TOK) return;
    bool ss = false;
    for (int i = 0; i < nseq; ++i) ss |= (cu[i] == t);
    float p;
    if (t == 0 || ss) {
        p = 1.0f;
    } else {
        const float cosv = dqk[t] * rsqrtf(nq2[t - 1] * nk2[t]);
        p = (1.0f - cosv) * 0.5f;
    }
    p = fminf(fmaxf(p, EPS_P), 1.0f - EPS_P);
    const bool b = (p >= 0.5f);
    a[t] = (ss || t == 0) ? 0.f : (b ? 1.f - p : 1.f);
    c[t] = b ? p : 0.f;
}

// ------- segmented EMA scan: h_t = a_t h_{t-1} + c_t z_t ------------------
__global__ void ema_scan_kernel(const float* __restrict__ z,
                                const float* __restrict__ a,
                                const float* __restrict__ c,
                                const int* __restrict__ cu,
                                float* __restrict__ out)
{
    __shared__ float sa[1024];
    __shared__ float sc[1024];
    const int seg = blockIdx.y;
    const int t0 = cu[seg], t1 = cu[seg + 1];
    const int ch = blockIdx.x * blockDim.x + threadIdx.x;
    float h = 0.f;
    for (int base = t0; base < t1; base += 1024) {
        const int len = min(1024, t1 - base);
        __syncthreads();
        for (int i = threadIdx.x; i < len; i += blockDim.x) {
            sa[i] = a[base + i];
            sc[i] = c[base + i];
        }
        __syncthreads();
        for (int i = 0; i < len; ++i) {
            const size_t off = (size_t)(base + i) * DIM + ch;
            const float zv = z[off];
            h = fmaf(sa[i], h, sc[i] * zv);
            out[off] = h;
        }
    }
}

// ---------------- launch ----------------
extern "C" void kernel_launch(void* const* d_in, const int* in_sizes, int n_in,
                              void* d_out, int out_size)
{
    const float* x      = (const float*)d_in[0];
    const float* Wq     = (const float*)d_in[1];
    const float* Wk     = (const float*)d_in[2];
    const float* fc1    = (const float*)d_in[3];
    const float* fc2    = (const float*)d_in[4];
    const float* norm_w = (const float*)d_in[5];
    const int*   cu     = (const int*)d_in[6];
    float*       out    = (float*)d_out;
    const int nseq = in_sizes[6] - 1;

    __half *xhi, *xlo, *wqth, *wqtl, *wkth, *wktl, *fc1t, *fc2t, *xn, *s;
    float *q, *k, *z, *nq, *nk, *dqk, *a, *c;
    cudaGetSymbolAddress((void**)&xhi,  g_xhi);
    cudaGetSymbolAddress((void**)&xlo,  g_xlo);
    cudaGetSymbolAddress((void**)&wqth, g_wqth);
    cudaGetSymbolAddress((void**)&wqtl, g_wqtl);
    cudaGetSymbolAddress((void**)&wkth, g_wkth);
    cudaGetSymbolAddress((void**)&wktl, g_wktl);
    cudaGetSymbolAddress((void**)&fc1t, g_fc1t);
    cudaGetSymbolAddress((void**)&fc2t, g_fc2t);
    cudaGetSymbolAddress((void**)&xn,   g_xn);
    cudaGetSymbolAddress((void**)&s,    g_s);
    cudaGetSymbolAddress((void**)&q,    g_q);
    cudaGetSymbolAddress((void**)&k,    g_k);
    cudaGetSymbolAddress((void**)&z,    g_z);
    cudaGetSymbolAddress((void**)&nq,   g_nq);
    cudaGetSymbolAddress((void**)&nk,   g_nk);
    cudaGetSymbolAddress((void**)&dqk,  g_dqk);
    cudaGetSymbolAddress((void**)&a,    g_a);
    cudaGetSymbolAddress((void**)&c,    g_c);

    // stage sizes (fp16, SKH=40): q/k 384 rows, others 256 rows; 2 stages
    const int SMEM_QK = 2 * 384 * SKH * 2;   // 61440 B
    const int SMEM_G  = 2 * 256 * SKH * 2;   // 40960 B
    cudaFuncSetAttribute((const void*)gemm16<64, true, false>,
                         cudaFuncAttributeMaxDynamicSharedMemorySize, SMEM_QK);
    cudaFuncSetAttribute((const void*)gemm16<64, false, true>,
                         cudaFuncAttributeMaxDynamicSharedMemorySize, SMEM_G);
    cudaFuncSetAttribute((const void*)gemm16<128, false, false>,
                         cudaFuncAttributeMaxDynamicSharedMemorySize, SMEM_G);

    // ---- pre-passes: fp16 splits + transposed fp16 weights ----
    {
        const size_t n = (size_t)T_TOK * DIM;
        split16<<<(unsigned)((n + 255) / 256), 256>>>(x, xhi, xlo);
    }
    tsplit16<<<dim3(DIM / 32, DIM / 32), dim3(32, 8)>>>(Wq, wqth, wqtl, DIM, DIM);
    tsplit16<<<dim3(DIM / 32, DIM / 32), dim3(32, 8)>>>(Wk, wkth, wktl, DIM, DIM);
    t16<<<dim3(2 * HID / 32, DIM / 32), dim3(32, 8)>>>(fc1, fc1t, DIM, 2 * HID);
    t16<<<dim3(DIM / 32, HID / 32), dim3(32, 8)>>>(fc2, fc2t, HID, DIM);

    // ---- q, k via 3-term fp16 split GEMM (sign-critical path) ----
    gemm16<64, true, false><<<(T_TOK / 128) * (DIM / 64), 256, SMEM_QK>>>(
        xhi, xlo, wqth, wqtl, nullptr, q, nullptr, DIM, DIM, T_TOK / 128);
    gemm16<64, true, false><<<(T_TOK / 128) * (DIM / 64), 256, SMEM_QK>>>(
        xhi, xlo, wkth, wktl, nullptr, k, nullptr, DIM, DIM, T_TOK / 128);

    // boundary statistics and scan coefficients
    qkstats_kernel<<<T_TOK, 256>>>(q, k, nq, nk, dqk);
    pcoef_kernel<<<T_TOK / 256, 256>>>(nq, nk, dqk, cu, nseq, a, c);

    // xn = rmsnorm(x)  (fp16)
    rmsnorm_kernel<<<T_TOK, 256>>>(x, norm_w, xn);

    // s = silu(xn@fc1_g) * (xn@fc1_h)   -- fused fc1 + SwiGLU (fp16 out)
    gemm16<64, false, true><<<(T_TOK / 128) * (HID / 64), 256, SMEM_G>>>(
        xn, nullptr, fc1t, nullptr, nullptr, nullptr, s, HID, DIM, T_TOK / 128);

    // z = x + s @ fc2  (fp32 out)
    gemm16<128, false, false><<<(T_TOK / 128) * (DIM / 128), 256, SMEM_G>>>(
        s, nullptr, fc2t, nullptr, x, z, nullptr, DIM, HID, T_TOK / 128);

    // segmented EMA scan -> out
    ema_scan_kernel<<<dim3(DIM / 256, nseq), 256>>>(z, a, c, cu, out);
}